// round 7
// baseline (speedup 1.0000x reference)
#include <cuda_runtime.h>
#include <cuda_fp16.h>
#include <cstdint>

#define DIMD  1024
#define BATCH 8
#define SEQ   2048

// ---------------------------------------------------------------------------
// Scratch (static device memory — no allocations)
// ---------------------------------------------------------------------------
__device__ __half g_xh  [(size_t)BATCH * SEQ * DIMD];      // x fp16
__device__ __half g_Wc  [(size_t)2 * DIMD * DIMD];         // [W1;W2] fp16
__device__ float  g_bc  [2 * DIMD];                        // [b1;b2] fp32
__device__ __half g_VKh [(size_t)BATCH * SEQ * 2 * DIMD];  // cols 0-1023 V(==Q), 1024-2047 K
__device__ __half g_VTh [(size_t)BATCH * SEQ * DIMD];      // V^T [B,D,S]
__device__ __half g_Sh  [(size_t)BATCH * SEQ * SEQ];       // scores / probs fp16

// ---------------------------------------------------------------------------
// Helpers
// ---------------------------------------------------------------------------
__device__ __forceinline__ uint32_t smem_u32(const void* p) {
    return (uint32_t)__cvta_generic_to_shared(p);
}
// SW64 swizzle for 64-byte rows: bits[5:4] ^= bits[8:7]
__device__ __forceinline__ uint32_t swz64(uint32_t o) { return o ^ ((o >> 3) & 0x30); }

__device__ __forceinline__ void cp_async16(uint32_t dst, const void* src) {
    asm volatile("cp.async.cg.shared.global [%0], [%1], 16;" :: "r"(dst), "l"(src));
}
__device__ __forceinline__ void cp_commit() {
    asm volatile("cp.async.commit_group;" ::: "memory");
}
__device__ __forceinline__ void cp_wait4() {
    asm volatile("cp.async.wait_group 4;" ::: "memory");
}
__device__ __forceinline__ void ldsm_x4(uint32_t* r, uint32_t addr) {
    asm volatile("ldmatrix.sync.aligned.m8n8.x4.shared.b16 {%0,%1,%2,%3}, [%4];"
                 : "=r"(r[0]), "=r"(r[1]), "=r"(r[2]), "=r"(r[3]) : "r"(addr));
}
__device__ __forceinline__ void mma16816(float* c, const uint32_t* a,
                                         uint32_t b0, uint32_t b1) {
    asm volatile("mma.sync.aligned.m16n8k16.row.col.f32.f16.f16.f32 "
                 "{%0,%1,%2,%3}, {%4,%5,%6,%7}, {%8,%9}, {%0,%1,%2,%3};"
                 : "+f"(c[0]), "+f"(c[1]), "+f"(c[2]), "+f"(c[3])
                 : "r"(a[0]), "r"(a[1]), "r"(a[2]), "r"(a[3]), "r"(b0), "r"(b1));
}

// ---------------------------------------------------------------------------
// Persistent fp16 tensor-core GEMM: C = alpha * A @ B^T (+bias)  (NT)
// Block tile 128x128, BK=32 halfs, 6-stage cp.async ring spanning tiles,
// 128 threads (4 warps, 2x2), warp tile 64x64, 2 CTAs/SM, grid = 296.
// Tile mapping: tile -> bz = tile>>tpz_shift; rem -> by = rem>>npx_shift,
//               bx = rem & (npx-1).  All shifts are powers of two.
// mode 0: half out + fp32 bias.  mode 1: float out.  mode 2: half out.
// ---------------------------------------------------------------------------
#define BM 128
#define BN 128
#define BKH 32
#define STG 16384          // (128 + 128) rows * 64 bytes
#define NSTAGE 6
#define LOOK 5

__global__ __launch_bounds__(128, 2)
void mm_h16(const __half* __restrict__ A, const __half* __restrict__ B,
            const float* __restrict__ bias, void* __restrict__ Cout,
            int lda, int ldb, int ldc,
            size_t zA, size_t zB, size_t zC,
            int ntiles, int npx_shift, int tpz_shift, int tshift,
            float alpha, int mode)
{
    extern __shared__ char smem[];
    const uint32_t sbase = smem_u32(smem);
    const int tid = threadIdx.x;
    const int wid = tid >> 5;
    const int lane = tid & 31;
    const int bid = blockIdx.x;
    const int ncta = gridDim.x;

    const int T = 1 << tshift;
    const int ntloc = (ntiles - bid + ncta - 1) / ncta;   // tiles for this CTA
    const int G = ntloc << tshift;                        // total mainloop iters

    const int r0 = tid >> 2;
    const int kc = tid & 3;
    const uint32_t d0 = swz64((uint32_t)(r0 * 64 + kc * 16));

    // Address of per-thread load base for global iteration q
#define ADDR(q, pa_, pb_) do { \
        int kq_ = (q) >> tshift; \
        int tq_ = (q) & (T - 1); \
        int tile_ = bid + kq_ * ncta; \
        int bz_ = tile_ >> tpz_shift; \
        int rem_ = tile_ & ((1 << tpz_shift) - 1); \
        int by_ = rem_ >> npx_shift; \
        int bx_ = rem_ & ((1 << npx_shift) - 1); \
        (pa_) = A + (size_t)bz_ * zA + (size_t)(by_ * BM + r0) * lda + kc * 8 + tq_ * BKH; \
        (pb_) = B + (size_t)bz_ * zB + (size_t)(bx_ * BN + r0) * ldb + kc * 8 + tq_ * BKH; \
    } while (0)

#define LOAD_STAGE(s, pa_, pb_) do { \
        uint32_t sb_ = sbase + (uint32_t)(s) * STG; \
        _Pragma("unroll") \
        for (int i_ = 0; i_ < 4; i_++) \
            cp_async16(sb_ + d0 + i_ * 2048u, (pa_) + (size_t)(32 * i_) * lda); \
        _Pragma("unroll") \
        for (int i_ = 0; i_ < 4; i_++) \
            cp_async16(sb_ + 8192u + d0 + i_ * 2048u, (pb_) + (size_t)(32 * i_) * ldb); \
    } while (0)

    // Prologue: stages 0..4
    #pragma unroll
    for (int p = 0; p < LOOK; p++) {
        if (p < G) {
            const __half *pa, *pb;
            ADDR(p, pa, pb);
            LOAD_STAGE(p, pa, pb);
        }
        cp_commit();
    }

    // --- compute plan: 4 warps, warp tile 64x64 ---
    const int wm = wid & 1;
    const int wn = wid >> 1;
    const int lr = lane & 15;
    const int lcb = (lane >> 4) * 16;

    uint32_t aoff[2][4], boff[2][4];
    #pragma unroll
    for (int ks = 0; ks < 2; ks++) {
        #pragma unroll
        for (int mi = 0; mi < 4; mi++)
            aoff[ks][mi] = swz64((uint32_t)((wm * 64 + mi * 16 + lr) * 64
                                            + ks * 32 + lcb));
        #pragma unroll
        for (int nb = 0; nb < 4; nb++)
            boff[ks][nb] = 8192u + swz64((uint32_t)((wn * 64 + nb * 16 + lr) * 64
                                                    + ks * 32 + lcb));
    }

#define LDFRAG(af, bf, sa_, ks_) do { \
        _Pragma("unroll") \
        for (int mi_ = 0; mi_ < 4; mi_++) ldsm_x4((af)[mi_], (sa_) + aoff[ks_][mi_]); \
        _Pragma("unroll") \
        for (int nb_ = 0; nb_ < 4; nb_++) ldsm_x4((bf)[nb_], (sa_) + boff[ks_][nb_]); \
    } while (0)

#define MMABLK(af, bf) do { \
        _Pragma("unroll") \
        for (int mi_ = 0; mi_ < 4; mi_++) \
            _Pragma("unroll") \
            for (int ni_ = 0; ni_ < 8; ni_++) \
                mma16816(acc[mi_][ni_], (af)[mi_], \
                         (bf)[ni_ >> 1][ni_ & 1], (bf)[ni_ >> 1][(ni_ & 1) + 2]); \
    } while (0)

    float acc[4][8][4] = {};
    uint32_t a0[4][4], b0[4][4], a1[4][4], b1[4][4];

    const int er = lane >> 2;
    const int ec = (lane & 3) * 2;

    cp_wait4();
    __syncthreads();
    LDFRAG(a0, b0, sbase, 0);

    int g = 0;
    int stg = 0, stl = LOOK;           // current stage, lookahead stage

    for (int k = 0; k < ntloc; k++) {
        // Current tile coords (for epilogue)
        const int tile = bid + k * ncta;
        const int bz = tile >> tpz_shift;
        const int rem = tile & ((1 << tpz_shift) - 1);
        const int tm = (rem >> npx_shift) * BM;
        const int tn = (rem & ((1 << npx_shift) - 1)) * BN;

        for (int t = 0; t < T; t++, g++) {
            const uint32_t sa = sbase + (uint32_t)stg * STG;

            LDFRAG(a1, b1, sa, 1);
            MMABLK(a0, b0);

            if (g + LOOK < G) {
                const __half *pa, *pb;
                ADDR(g + LOOK, pa, pb);
                LOAD_STAGE(stl, pa, pb);
            }
            cp_commit();
            cp_wait4();
            __syncthreads();

            stg = (stg == NSTAGE - 1) ? 0 : stg + 1;
            stl = (stl == NSTAGE - 1) ? 0 : stl + 1;

            if (g + 1 < G)
                LDFRAG(a0, b0, sbase + (uint32_t)stg * STG, 0);
            MMABLK(a1, b1);
        }

        // --- epilogue for this tile ---
        if (mode == 1) {
            float* C = (float*)Cout + (size_t)bz * zC;
            #pragma unroll
            for (int mi = 0; mi < 4; mi++) {
                #pragma unroll
                for (int ni = 0; ni < 8; ni++) {
                    int m0 = tm + wm * 64 + mi * 16 + er;
                    int n0 = tn + wn * 64 + ni * 8 + ec;
                    float* c = acc[mi][ni];
                    *(float2*)(C + (size_t)m0 * ldc + n0) =
                        make_float2(c[0] * alpha, c[1] * alpha);
                    *(float2*)(C + (size_t)(m0 + 8) * ldc + n0) =
                        make_float2(c[2] * alpha, c[3] * alpha);
                }
            }
        } else {
            __half* C = (__half*)Cout + (size_t)bz * zC;
            #pragma unroll
            for (int mi = 0; mi < 4; mi++) {
                #pragma unroll
                for (int ni = 0; ni < 8; ni++) {
                    int m0 = tm + wm * 64 + mi * 16 + er;
                    int n0 = tn + wn * 64 + ni * 8 + ec;
                    float bx = 0.f, by = 0.f;
                    if (mode == 0) { bx = bias[n0]; by = bias[n0 + 1]; }
                    float* c = acc[mi][ni];
                    *(__half2*)(C + (size_t)m0 * ldc + n0) =
                        __floats2half2_rn(c[0] * alpha + bx, c[1] * alpha + by);
                    *(__half2*)(C + (size_t)(m0 + 8) * ldc + n0) =
                        __floats2half2_rn(c[2] * alpha + bx, c[3] * alpha + by);
                }
            }
        }

        // reset accumulators for next tile
        #pragma unroll
        for (int mi = 0; mi < 4; mi++)
            #pragma unroll
            for (int ni = 0; ni < 8; ni++)
                #pragma unroll
                for (int q = 0; q < 4; q++)
                    acc[mi][ni][q] = 0.0f;
    }
#undef ADDR
#undef LOAD_STAGE
#undef LDFRAG
#undef MMABLK
}

// ---------------------------------------------------------------------------
// fp32 -> fp16 conversion (vectorized)
// ---------------------------------------------------------------------------
__global__ __launch_bounds__(256)
void f2h(const float* __restrict__ in, __half* __restrict__ out, long long n4)
{
    long long i = (long long)blockIdx.x * blockDim.x + threadIdx.x;
    long long stride = (long long)gridDim.x * blockDim.x;
    for (; i < n4; i += stride) {
        float4 v = ((const float4*)in)[i];
        ((__half2*)out)[2 * i + 0] = __floats2half2_rn(v.x, v.y);
        ((__half2*)out)[2 * i + 1] = __floats2half2_rn(v.z, v.w);
    }
}

// ---------------------------------------------------------------------------
// Batched fp16 transpose with input stride: in[b, s, d] (ld ldin) -> out[b, d, s]
// ---------------------------------------------------------------------------
__global__ __launch_bounds__(256)
void transpose_h(const __half* __restrict__ in, __half* __restrict__ out, int ldin)
{
    __shared__ __half t[32][33];
    const int b = blockIdx.z;
    const __half* I = in + (size_t)b * SEQ * ldin;
    __half* O = out + (size_t)b * SEQ * DIMD;
    const int d0 = blockIdx.x * 32, s0 = blockIdx.y * 32;
    #pragma unroll
    for (int i = threadIdx.y; i < 32; i += 8)
        t[i][threadIdx.x] = I[(size_t)(s0 + i) * ldin + d0 + threadIdx.x];
    __syncthreads();
    #pragma unroll
    for (int i = threadIdx.y; i < 32; i += 8)
        O[(size_t)(d0 + i) * SEQ + s0 + threadIdx.x] = t[threadIdx.x][i];
}

// ---------------------------------------------------------------------------
// Row softmax over fp16 scores, in place (fp32 math inside).
// ---------------------------------------------------------------------------
__global__ __launch_bounds__(256)
void softmax_rows_h(__half* __restrict__ S)
{
    const long long row = blockIdx.x;
    __half* p = S + row * (long long)SEQ;
    const int tid = threadIdx.x;
    const int lane = tid & 31;
    const int warp = tid >> 5;

    __shared__ float red_max[8];
    __shared__ float red_sum[8];

    float v[8];
    {
        uint4 raw = *(const uint4*)(p + tid * 8);
        const __half2* h = (const __half2*)&raw;
        #pragma unroll
        for (int i = 0; i < 4; i++) {
            float2 f = __half22float2(h[i]);
            v[2 * i] = f.x; v[2 * i + 1] = f.y;
        }
    }
    float m = v[0];
    #pragma unroll
    for (int i = 1; i < 8; i++) m = fmaxf(m, v[i]);
    #pragma unroll
    for (int o = 16; o > 0; o >>= 1) m = fmaxf(m, __shfl_xor_sync(0xffffffffu, m, o));
    if (lane == 0) red_max[warp] = m;
    __syncthreads();
    float mall = red_max[0];
    #pragma unroll
    for (int w = 1; w < 8; w++) mall = fmaxf(mall, red_max[w]);

    float s = 0.0f;
    #pragma unroll
    for (int i = 0; i < 8; i++) {
        v[i] = __expf(v[i] - mall);
        s += v[i];
    }
    #pragma unroll
    for (int o = 16; o > 0; o >>= 1) s += __shfl_xor_sync(0xffffffffu, s, o);
    if (lane == 0) red_sum[warp] = s;
    __syncthreads();
    float sall = 0.0f;
    #pragma unroll
    for (int w = 0; w < 8; w++) sall += red_sum[w];

    const float inv = __frcp_rn(sall);
    {
        uint4 raw;
        __half2* h = (__half2*)&raw;
        #pragma unroll
        for (int i = 0; i < 4; i++)
            h[i] = __floats2half2_rn(v[2 * i] * inv, v[2 * i + 1] * inv);
        *(uint4*)(p + tid * 8) = raw;
    }
}

// ---------------------------------------------------------------------------
// Launch
// ---------------------------------------------------------------------------
extern "C" void kernel_launch(void* const* d_in, const int* in_sizes, int n_in,
                              void* d_out, int out_size)
{
    const float* x  = (const float*)d_in[0];
    const float* W1 = (const float*)d_in[1];
    const float* b1 = (const float*)d_in[2];
    const float* W2 = (const float*)d_in[3];
    const float* b2 = (const float*)d_in[4];
    float* out = (float*)d_out;

    __half *pxh, *pWc, *pVKh, *pVTh, *pSh;
    float *pbc;
    cudaGetSymbolAddress((void**)&pxh,  g_xh);
    cudaGetSymbolAddress((void**)&pWc,  g_Wc);
    cudaGetSymbolAddress((void**)&pbc,  g_bc);
    cudaGetSymbolAddress((void**)&pVKh, g_VKh);
    cudaGetSymbolAddress((void**)&pVTh, g_VTh);
    cudaGetSymbolAddress((void**)&pSh,  g_Sh);

    const int SMEM_SZ = NSTAGE * STG;  // 98304 per CTA
    cudaFuncSetAttribute(mm_h16, cudaFuncAttributeMaxDynamicSharedMemorySize, SMEM_SZ);

    const int NCTA = 296;              // 148 SMs x 2 CTAs
    const float scale = 1.0f / 32.0f;  // 1/sqrt(1024)

    // 1. fp32 -> fp16 inputs; concat weights [W1;W2] and biases
    f2h<<<2048, 256>>>(x,  pxh, (long long)BATCH * SEQ * DIMD / 4);
    f2h<<<512,  256>>>(W1, pWc,                      (long long)DIMD * DIMD / 4);
    f2h<<<512,  256>>>(W2, pWc + (size_t)DIMD * DIMD, (long long)DIMD * DIMD / 4);
    cudaMemcpyAsync(pbc,        b1, DIMD * sizeof(float), cudaMemcpyDeviceToDevice);
    cudaMemcpyAsync(pbc + DIMD, b2, DIMD * sizeof(float), cudaMemcpyDeviceToDevice);

    // 2. [V | K] = fp16(x @ [W1;W2]^T + [b1;b2])   M=16384, N=2048, K=1024
    //    tiles: npy=128, npx=16 -> 2048 tiles, T=32
    mm_h16<<<NCTA, 128, SMEM_SZ>>>(
        pxh, pWc, pbc, pVKh,
        DIMD, DIMD, 2 * DIMD,
        0, 0, 0,
        2048, /*npx_shift=*/4, /*tpz_shift=*/11, /*tshift=*/5,
        1.0f, 0);

    // 3. VT = V^T per batch (V strided in VKh)
    transpose_h<<<dim3(DIMD / 32, SEQ / 32, BATCH), dim3(32, 8)>>>(pVKh, pVTh, 2 * DIMD);

    // 4. scores[b,k,q] = fp16(scale * K[b,k,:] . V[b,q,:])
    //    A = K (offset DIMD in VKh), B = V; tiles: 16x16x8 = 2048, T=32
    mm_h16<<<NCTA, 128, SMEM_SZ>>>(
        pVKh + DIMD, pVKh, nullptr, pSh,
        2 * DIMD, 2 * DIMD, SEQ,
        (size_t)SEQ * 2 * DIMD, (size_t)SEQ * 2 * DIMD, (size_t)SEQ * SEQ,
        2048, /*npx_shift=*/4, /*tpz_shift=*/8, /*tshift=*/5,
        scale, 2);

    // 5. softmax in place (fp16)
    softmax_rows_h<<<BATCH * SEQ, 256>>>(pSh);

    // 6. out[b,k,d] = P[b,k,:] @ VT[b,d,:]^T  (fp32 out)
    //    tiles: npx=8, npy=16, z=8 -> 1024, T=64
    mm_h16<<<NCTA, 128, SMEM_SZ>>>(
        pSh, pVTh, nullptr, out,
        SEQ, SEQ, DIMD,
        (size_t)SEQ * SEQ, (size_t)SEQ * DIMD, (size_t)SEQ * DIMD,
        1024, /*npx_shift=*/3, /*tpz_shift=*/7, /*tshift=*/6,
        1.0f, 1);
}

// round 8
// speedup vs baseline: 1.1427x; 1.1427x over previous
#include <cuda_runtime.h>
#include <cuda_fp16.h>
#include <cstdint>

#define DIMD  1024
#define BATCH 8
#define SEQ   2048

// ---------------------------------------------------------------------------
// Scratch (static device memory — no allocations)
// ---------------------------------------------------------------------------
__device__ __half g_xh  [(size_t)BATCH * SEQ * DIMD];      // x fp16
__device__ __half g_Wc  [(size_t)2 * DIMD * DIMD];         // [W1;W2] fp16
__device__ float  g_bc  [2 * DIMD];                        // [b1;b2] fp32
__device__ __half g_VKh [(size_t)BATCH * SEQ * 2 * DIMD];  // cols 0-1023 V(==Q), 1024-2047 K
__device__ __half g_VTh [(size_t)BATCH * SEQ * DIMD];      // V^T [B,D,S]
__device__ __half g_Sh  [(size_t)BATCH * SEQ * SEQ];       // scores / probs fp16

// ---------------------------------------------------------------------------
// Helpers
// ---------------------------------------------------------------------------
__device__ __forceinline__ uint32_t smem_u32(const void* p) {
    return (uint32_t)__cvta_generic_to_shared(p);
}
// SW128 swizzle for 128-byte rows: bits[6:4] ^= bits[9:7]
__device__ __forceinline__ uint32_t swz(uint32_t o) { return o ^ ((o >> 3) & 0x70); }

__device__ __forceinline__ void cp_async16(uint32_t dst, const void* src) {
    asm volatile("cp.async.cg.shared.global [%0], [%1], 16;" :: "r"(dst), "l"(src));
}
__device__ __forceinline__ void cp_commit() {
    asm volatile("cp.async.commit_group;" ::: "memory");
}
__device__ __forceinline__ void cp_wait1() {
    asm volatile("cp.async.wait_group 1;" ::: "memory");
}
__device__ __forceinline__ void ldsm_x4(uint32_t* r, uint32_t addr) {
    asm volatile("ldmatrix.sync.aligned.m8n8.x4.shared.b16 {%0,%1,%2,%3}, [%4];"
                 : "=r"(r[0]), "=r"(r[1]), "=r"(r[2]), "=r"(r[3]) : "r"(addr));
}
__device__ __forceinline__ void mma16816(float* c, const uint32_t* a,
                                         uint32_t b0, uint32_t b1) {
    asm volatile("mma.sync.aligned.m16n8k16.row.col.f32.f16.f16.f32 "
                 "{%0,%1,%2,%3}, {%4,%5,%6,%7}, {%8,%9}, {%0,%1,%2,%3};"
                 : "+f"(c[0]), "+f"(c[1]), "+f"(c[2]), "+f"(c[3])
                 : "r"(a[0]), "r"(a[1]), "r"(a[2]), "r"(a[3]), "r"(b0), "r"(b1));
}

// ---------------------------------------------------------------------------
// fp16 tensor-core GEMM: C = alpha * A @ B^T (+bias)  (NT), generic ld/strides.
// Block tile 128x128, BK=64 halfs (128B rows, SW128), 3-stage cp.async ring,
// 128 threads (4 warps, 2x2), warp tile 64x64, 2 CTAs/SM,
// register double-buffered fragments, ONE barrier per 64-K iteration.
// mode 0: half out + fp32 bias.  mode 1: float out.  mode 2: half out.
// ---------------------------------------------------------------------------
#define BM 128
#define BN 128
#define BKH 64
#define STG 32768          // (128 + 128) rows * 128 bytes
#define NSTAGE 3

__global__ __launch_bounds__(128, 2)
void mm_h16(const __half* __restrict__ A, const __half* __restrict__ B,
            const float* __restrict__ bias, void* __restrict__ Cout,
            int lda, int ldb, int ldc,
            size_t zA, size_t zB, size_t zC,
            int K, float alpha, int mode)
{
    extern __shared__ char smem[];
    const uint32_t sbase = smem_u32(smem);
    const int tid = threadIdx.x;
    const int wid = tid >> 5;
    const int lane = tid & 31;

    const int bz = blockIdx.z;
    A += (size_t)bz * zA;
    B += (size_t)bz * zB;

    const int tile_m = blockIdx.y * BM;
    const int tile_n = blockIdx.x * BN;
    const int T = K / BKH;

    // --- loader plan: 2048 16B chunks/stage, 16 per thread (8 A + 8 B) ---
    const int r0 = tid >> 3;           // base row 0..15 (+16*i)
    const int kc = tid & 7;            // 16B column chunk within 128B row
    const __half* gA = A + (size_t)(tile_m + r0) * lda + kc * 8;
    const __half* gB = B + (size_t)(tile_n + r0) * ldb + kc * 8;
    const uint32_t d0 = swz((uint32_t)(r0 * 128 + kc * 16));   // +i*2048 rows (swz-invariant)

#define LOAD_STAGE(s, t) do { \
        uint32_t sb_ = sbase + (uint32_t)(s) * STG; \
        const __half* pa_ = gA + (size_t)(t) * BKH; \
        const __half* pb_ = gB + (size_t)(t) * BKH; \
        _Pragma("unroll") \
        for (int i_ = 0; i_ < 8; i_++) \
            cp_async16(sb_ + d0 + i_ * 2048u, pa_ + (size_t)(16 * i_) * lda); \
        _Pragma("unroll") \
        for (int i_ = 0; i_ < 8; i_++) \
            cp_async16(sb_ + 16384u + d0 + i_ * 2048u, pb_ + (size_t)(16 * i_) * ldb); \
    } while (0)

    // Prefetch stages 0,1
    #pragma unroll
    for (int p = 0; p < 2; p++) {
        if (p < T) LOAD_STAGE(p, p);
        cp_commit();
    }

    // --- compute plan: 4 warps, warp tile 64x64, ks = 0..3 sub-slices ---
    const int wm = wid & 1;
    const int wn = wid >> 1;
    const int lr = lane & 15;
    const int lcb = (lane >> 4) * 16;  // 0 or 16 (bit-disjoint from ks*32)

    uint32_t aoff0[4], boff0[4];
    #pragma unroll
    for (int mi = 0; mi < 4; mi++)
        aoff0[mi] = swz((uint32_t)((wm * 64 + mi * 16 + lr) * 128 + lcb));
    #pragma unroll
    for (int nb = 0; nb < 4; nb++)
        boff0[nb] = 16384u + swz((uint32_t)((wn * 64 + nb * 16 + lr) * 128 + lcb));

    // swz(base + ks*32) == swz(base) ^ (ks*32)  (bit-disjoint addition)
#define LDFRAG(af, bf, sa_, ks_) do { \
        _Pragma("unroll") \
        for (int mi_ = 0; mi_ < 4; mi_++) \
            ldsm_x4((af)[mi_], (sa_) + (aoff0[mi_] ^ (uint32_t)((ks_) * 32))); \
        _Pragma("unroll") \
        for (int nb_ = 0; nb_ < 4; nb_++) \
            ldsm_x4((bf)[nb_], (sa_) + (boff0[nb_] ^ (uint32_t)((ks_) * 32))); \
    } while (0)

#define MMABLK(af, bf) do { \
        _Pragma("unroll") \
        for (int mi_ = 0; mi_ < 4; mi_++) \
            _Pragma("unroll") \
            for (int ni_ = 0; ni_ < 8; ni_++) \
                mma16816(acc[mi_][ni_], (af)[mi_], \
                         (bf)[ni_ >> 1][ni_ & 1], (bf)[ni_ >> 1][(ni_ & 1) + 2]); \
    } while (0)

    float acc[4][8][4] = {};
    uint32_t a0[4][4], b0[4][4], a1[4][4], b1[4][4];

    cp_wait1();
    __syncthreads();
    LDFRAG(a0, b0, sbase, 0);          // stage 0, ks 0

    for (int t = 0; t < T; t++) {
        const uint32_t sa = sbase + (uint32_t)(t % NSTAGE) * STG;

        LDFRAG(a1, b1, sa, 1);
        MMABLK(a0, b0);                // ks 0
        LDFRAG(a0, b0, sa, 2);
        MMABLK(a1, b1);                // ks 1
        LDFRAG(a1, b1, sa, 3);
        MMABLK(a0, b0);                // ks 2

        if (t + 2 < T) LOAD_STAGE((t + 2) % NSTAGE, t + 2);
        cp_commit();
        cp_wait1();
        __syncthreads();

        if (t + 1 < T)
            LDFRAG(a0, b0, sbase + (uint32_t)((t + 1) % NSTAGE) * STG, 0);
        MMABLK(a1, b1);                // ks 3 (covers barrier + next-stage loads)
    }

    // --- epilogue ---
    const int er = lane >> 2;
    const int ec = (lane & 3) * 2;

    if (mode == 1) {
        float* C = (float*)Cout + (size_t)bz * zC;
        #pragma unroll
        for (int mi = 0; mi < 4; mi++) {
            #pragma unroll
            for (int ni = 0; ni < 8; ni++) {
                int m0 = tile_m + wm * 64 + mi * 16 + er;
                int n0 = tile_n + wn * 64 + ni * 8 + ec;
                float* c = acc[mi][ni];
                *(float2*)(C + (size_t)m0 * ldc + n0) =
                    make_float2(c[0] * alpha, c[1] * alpha);
                *(float2*)(C + (size_t)(m0 + 8) * ldc + n0) =
                    make_float2(c[2] * alpha, c[3] * alpha);
            }
        }
    } else {
        __half* C = (__half*)Cout + (size_t)bz * zC;
        #pragma unroll
        for (int mi = 0; mi < 4; mi++) {
            #pragma unroll
            for (int ni = 0; ni < 8; ni++) {
                int m0 = tile_m + wm * 64 + mi * 16 + er;
                int n0 = tile_n + wn * 64 + ni * 8 + ec;
                float bx = 0.f, by = 0.f;
                if (mode == 0) { bx = bias[n0]; by = bias[n0 + 1]; }
                float* c = acc[mi][ni];
                *(__half2*)(C + (size_t)m0 * ldc + n0) =
                    __floats2half2_rn(c[0] * alpha + bx, c[1] * alpha + by);
                *(__half2*)(C + (size_t)(m0 + 8) * ldc + n0) =
                    __floats2half2_rn(c[2] * alpha + bx, c[3] * alpha + by);
            }
        }
    }
#undef LOAD_STAGE
#undef LDFRAG
#undef MMABLK
}

// ---------------------------------------------------------------------------
// fp32 -> fp16 conversion (vectorized)
// ---------------------------------------------------------------------------
__global__ __launch_bounds__(256)
void f2h(const float* __restrict__ in, __half* __restrict__ out, long long n4)
{
    long long i = (long long)blockIdx.x * blockDim.x + threadIdx.x;
    long long stride = (long long)gridDim.x * blockDim.x;
    for (; i < n4; i += stride) {
        float4 v = ((const float4*)in)[i];
        ((__half2*)out)[2 * i + 0] = __floats2half2_rn(v.x, v.y);
        ((__half2*)out)[2 * i + 1] = __floats2half2_rn(v.z, v.w);
    }
}

// ---------------------------------------------------------------------------
// Batched fp16 transpose with input stride: in[b,s,d] (ld ldin) -> out[b,d,s]
// ---------------------------------------------------------------------------
__global__ __launch_bounds__(256)
void transpose_h(const __half* __restrict__ in, __half* __restrict__ out, int ldin)
{
    __shared__ __half t[32][33];
    const int b = blockIdx.z;
    const __half* I = in + (size_t)b * SEQ * ldin;
    __half* O = out + (size_t)b * SEQ * DIMD;
    const int d0 = blockIdx.x * 32, s0 = blockIdx.y * 32;
    #pragma unroll
    for (int i = threadIdx.y; i < 32; i += 8)
        t[i][threadIdx.x] = I[(size_t)(s0 + i) * ldin + d0 + threadIdx.x];
    __syncthreads();
    #pragma unroll
    for (int i = threadIdx.y; i < 32; i += 8)
        O[(size_t)(d0 + i) * SEQ + s0 + threadIdx.x] = t[threadIdx.x][i];
}

// ---------------------------------------------------------------------------
// Row softmax over fp16 scores, in place (fp32 math inside).
// ---------------------------------------------------------------------------
__global__ __launch_bounds__(256)
void softmax_rows_h(__half* __restrict__ S)
{
    const long long row = blockIdx.x;
    __half* p = S + row * (long long)SEQ;
    const int tid = threadIdx.x;
    const int lane = tid & 31;
    const int warp = tid >> 5;

    __shared__ float red_max[8];
    __shared__ float red_sum[8];

    float v[8];
    {
        uint4 raw = *(const uint4*)(p + tid * 8);
        const __half2* h = (const __half2*)&raw;
        #pragma unroll
        for (int i = 0; i < 4; i++) {
            float2 f = __half22float2(h[i]);
            v[2 * i] = f.x; v[2 * i + 1] = f.y;
        }
    }
    float m = v[0];
    #pragma unroll
    for (int i = 1; i < 8; i++) m = fmaxf(m, v[i]);
    #pragma unroll
    for (int o = 16; o > 0; o >>= 1) m = fmaxf(m, __shfl_xor_sync(0xffffffffu, m, o));
    if (lane == 0) red_max[warp] = m;
    __syncthreads();
    float mall = red_max[0];
    #pragma unroll
    for (int w = 1; w < 8; w++) mall = fmaxf(mall, red_max[w]);

    float s = 0.0f;
    #pragma unroll
    for (int i = 0; i < 8; i++) {
        v[i] = __expf(v[i] - mall);
        s += v[i];
    }
    #pragma unroll
    for (int o = 16; o > 0; o >>= 1) s += __shfl_xor_sync(0xffffffffu, s, o);
    if (lane == 0) red_sum[warp] = s;
    __syncthreads();
    float sall = 0.0f;
    #pragma unroll
    for (int w = 0; w < 8; w++) sall += red_sum[w];

    const float inv = __frcp_rn(sall);
    {
        uint4 raw;
        __half2* h = (__half2*)&raw;
        #pragma unroll
        for (int i = 0; i < 4; i++)
            h[i] = __floats2half2_rn(v[2 * i] * inv, v[2 * i + 1] * inv);
        *(uint4*)(p + tid * 8) = raw;
    }
}

// ---------------------------------------------------------------------------
// Launch
// ---------------------------------------------------------------------------
extern "C" void kernel_launch(void* const* d_in, const int* in_sizes, int n_in,
                              void* d_out, int out_size)
{
    const float* x  = (const float*)d_in[0];
    const float* W1 = (const float*)d_in[1];
    const float* b1 = (const float*)d_in[2];
    const float* W2 = (const float*)d_in[3];
    const float* b2 = (const float*)d_in[4];
    float* out = (float*)d_out;

    __half *pxh, *pWc, *pVKh, *pVTh, *pSh;
    float *pbc;
    cudaGetSymbolAddress((void**)&pxh,  g_xh);
    cudaGetSymbolAddress((void**)&pWc,  g_Wc);
    cudaGetSymbolAddress((void**)&pbc,  g_bc);
    cudaGetSymbolAddress((void**)&pVKh, g_VKh);
    cudaGetSymbolAddress((void**)&pVTh, g_VTh);
    cudaGetSymbolAddress((void**)&pSh,  g_Sh);

    const int SMEM_SZ = NSTAGE * STG;  // 98304 per CTA
    cudaFuncSetAttribute(mm_h16, cudaFuncAttributeMaxDynamicSharedMemorySize, SMEM_SZ);

    const float scale = 1.0f / 32.0f;  // 1/sqrt(1024)

    // 1. fp32 -> fp16 inputs; concat weights [W1;W2] and biases
    f2h<<<2048, 256>>>(x,  pxh, (long long)BATCH * SEQ * DIMD / 4);
    f2h<<<512,  256>>>(W1, pWc,                       (long long)DIMD * DIMD / 4);
    f2h<<<512,  256>>>(W2, pWc + (size_t)DIMD * DIMD, (long long)DIMD * DIMD / 4);
    cudaMemcpyAsync(pbc,        b1, DIMD * sizeof(float), cudaMemcpyDeviceToDevice);
    cudaMemcpyAsync(pbc + DIMD, b2, DIMD * sizeof(float), cudaMemcpyDeviceToDevice);

    // 2. [V | K] = fp16(x @ [W1;W2]^T + [b1;b2]) : M=16384, N=2048, K=1024
    mm_h16<<<dim3(2 * DIMD / BN, BATCH * SEQ / BM, 1), 128, SMEM_SZ>>>(
        pxh, pWc, pbc, pVKh,
        DIMD, DIMD, 2 * DIMD, 0, 0, 0,
        DIMD, 1.0f, 0);

    // 3. VT = V^T per batch (V strided in VKh)
    transpose_h<<<dim3(DIMD / 32, SEQ / 32, BATCH), dim3(32, 8)>>>(pVKh, pVTh, 2 * DIMD);

    // 4. scores[b,k,q] = fp16(scale * K[b,k,:] . V[b,q,:])
    mm_h16<<<dim3(SEQ / BN, SEQ / BM, BATCH), 128, SMEM_SZ>>>(
        pVKh + DIMD, pVKh, nullptr, pSh,
        2 * DIMD, 2 * DIMD, SEQ,
        (size_t)SEQ * 2 * DIMD, (size_t)SEQ * 2 * DIMD, (size_t)SEQ * SEQ,
        DIMD, scale, 2);

    // 5. softmax in place (fp16)
    softmax_rows_h<<<BATCH * SEQ, 256>>>(pSh);

    // 6. out[b,k,d] = P[b,k,:] @ VT[b,d,:]^T  (fp32 out)
    mm_h16<<<dim3(DIMD / BN, SEQ / BM, BATCH), 128, SMEM_SZ>>>(
        pSh, pVTh, nullptr, out,
        SEQ, SEQ, DIMD,
        (size_t)SEQ * SEQ, (size_t)SEQ * DIMD, (size_t)SEQ * DIMD,
        SEQ, 1.0f, 1);
}

// round 9
// speedup vs baseline: 1.2384x; 1.0838x over previous
#include <cuda_runtime.h>
#include <cuda_fp16.h>
#include <cstdint>

#define DIMD  1024
#define BATCH 8
#define SEQ   2048

// ---------------------------------------------------------------------------
// Scratch (static device memory — no allocations)
// ---------------------------------------------------------------------------
__device__ __half g_xh  [(size_t)BATCH * SEQ * DIMD];      // x fp16
__device__ __half g_Wc  [(size_t)2 * DIMD * DIMD];         // [W1;W2] fp16
__device__ float  g_bc  [2 * DIMD];                        // [b1;b2] fp32
__device__ __half g_VKh [(size_t)BATCH * SEQ * 2 * DIMD];  // cols 0-1023 V(==Q), 1024-2047 K
__device__ __half g_Sh  [(size_t)BATCH * SEQ * SEQ];       // scores / probs fp16

// ---------------------------------------------------------------------------
// Helpers
// ---------------------------------------------------------------------------
__device__ __forceinline__ uint32_t smem_u32(const void* p) {
    return (uint32_t)__cvta_generic_to_shared(p);
}
// SW128 swizzle for 128-byte rows: bits[6:4] ^= bits[9:7]
__device__ __forceinline__ uint32_t swz(uint32_t o) { return o ^ ((o >> 3) & 0x70); }
// swizzle for 256-byte rows: bits[6:4] ^= bits[10:8]
__device__ __forceinline__ uint32_t swzB(uint32_t o) { return o ^ ((o >> 4) & 0x70); }

__device__ __forceinline__ void cp_async16(uint32_t dst, const void* src) {
    asm volatile("cp.async.cg.shared.global [%0], [%1], 16;" :: "r"(dst), "l"(src));
}
__device__ __forceinline__ void cp_commit() {
    asm volatile("cp.async.commit_group;" ::: "memory");
}
__device__ __forceinline__ void cp_wait1() {
    asm volatile("cp.async.wait_group 1;" ::: "memory");
}
__device__ __forceinline__ void ldsm_x4(uint32_t* r, uint32_t addr) {
    asm volatile("ldmatrix.sync.aligned.m8n8.x4.shared.b16 {%0,%1,%2,%3}, [%4];"
                 : "=r"(r[0]), "=r"(r[1]), "=r"(r[2]), "=r"(r[3]) : "r"(addr));
}
__device__ __forceinline__ void ldsm_x4_t(uint32_t* r, uint32_t addr) {
    asm volatile("ldmatrix.sync.aligned.m8n8.x4.trans.shared.b16 {%0,%1,%2,%3}, [%4];"
                 : "=r"(r[0]), "=r"(r[1]), "=r"(r[2]), "=r"(r[3]) : "r"(addr));
}
__device__ __forceinline__ void mma16816(float* c, const uint32_t* a,
                                         uint32_t b0, uint32_t b1) {
    asm volatile("mma.sync.aligned.m16n8k16.row.col.f32.f16.f16.f32 "
                 "{%0,%1,%2,%3}, {%4,%5,%6,%7}, {%8,%9}, {%0,%1,%2,%3};"
                 : "+f"(c[0]), "+f"(c[1]), "+f"(c[2]), "+f"(c[3])
                 : "r"(a[0]), "r"(a[1]), "r"(a[2]), "r"(a[3]), "r"(b0), "r"(b1));
}

// ---------------------------------------------------------------------------
// fp16 tensor-core GEMM, templated on B layout:
//   TRB=0 (NT): C = alpha * A[M,K] @ B[N,K]^T   (B rows k-contiguous)
//   TRB=1 (NN): C = alpha * A[M,K] @ B[K,N]     (B rows n-contiguous, ldsm.trans)
// Block tile 128x128, BK=64 halfs, 3-stage cp.async ring, 128 threads
// (4 warps, 2x2), warp tile 64x64, 2 CTAs/SM, register double-buffering,
// one barrier per 64-K iteration.
// mode 0: half out + fp32 bias.  mode 1: float out.  mode 2: half out.
// ---------------------------------------------------------------------------
#define BM 128
#define BN 128
#define BKH 64
#define STG 32768          // A: 128 rows*128B + B: 16KB
#define NSTAGE 3

template<int TRB>
__global__ __launch_bounds__(128, 2)
void mm_h16(const __half* __restrict__ A, const __half* __restrict__ B,
            const float* __restrict__ bias, void* __restrict__ Cout,
            int lda, int ldb, int ldc,
            size_t zA, size_t zB, size_t zC,
            int K, float alpha, int mode)
{
    extern __shared__ char smem[];
    const uint32_t sbase = smem_u32(smem);
    const int tid = threadIdx.x;
    const int wid = tid >> 5;
    const int lane = tid & 31;

    const int bz = blockIdx.z;
    A += (size_t)bz * zA;
    B += (size_t)bz * zB;

    const int tile_m = blockIdx.y * BM;
    const int tile_n = blockIdx.x * BN;
    const int T = K / BKH;

    // --- A loader: 1024 16B chunks/stage, 8 per thread ---
    const int rA = tid >> 3;           // base row 0..15 (+16*i)
    const int kcA = tid & 7;
    const __half* gA = A + (size_t)(tile_m + rA) * lda + kcA * 8;
    const uint32_t dA = swz((uint32_t)(rA * 128 + kcA * 16));  // +i*2048 (swz-invariant)

    // --- B loader ---
    // NT: B[N,K]: 128 rows x 128B, same pattern as A.
    // NN: B[K,N]: 64 rows x 256B; thread -> row (tid>>4)+8i, 16B col (tid&15).
    const __half* gB;
    uint32_t dB;
    if (TRB == 0) {
        gB = B + (size_t)(tile_n + rA) * ldb + kcA * 8;
        dB = 16384u + swz((uint32_t)(rA * 128 + kcA * 16));
    } else {
        const int rB = tid >> 4;       // 0..7 (+8*i)
        const int cB = tid & 15;
        gB = B + (size_t)rB * ldb + tile_n + cB * 8;
        dB = 16384u + swzB((uint32_t)(rB * 256 + cB * 16));    // +i*2048 (swz-invariant)
    }

#define LOAD_STAGE(s, t) do { \
        uint32_t sb_ = sbase + (uint32_t)(s) * STG; \
        const __half* pa_ = gA + (size_t)(t) * BKH; \
        _Pragma("unroll") \
        for (int i_ = 0; i_ < 8; i_++) \
            cp_async16(sb_ + dA + i_ * 2048u, pa_ + (size_t)(16 * i_) * lda); \
        if (TRB == 0) { \
            const __half* pb_ = gB + (size_t)(t) * BKH; \
            _Pragma("unroll") \
            for (int i_ = 0; i_ < 8; i_++) \
                cp_async16(sb_ + dB + i_ * 2048u, pb_ + (size_t)(16 * i_) * ldb); \
        } else { \
            const __half* pb_ = gB + (size_t)(t) * BKH * ldb; \
            _Pragma("unroll") \
            for (int i_ = 0; i_ < 8; i_++) \
                cp_async16(sb_ + dB + i_ * 2048u, pb_ + (size_t)(8 * i_) * ldb); \
        } \
    } while (0)

    // Prefetch stages 0,1
    #pragma unroll
    for (int p = 0; p < 2; p++) {
        if (p < T) LOAD_STAGE(p, p);
        cp_commit();
    }

    // --- compute plan: 4 warps, warp tile 64x64, ks = 0..3 sub-slices ---
    const int wm = wid & 1;
    const int wn = wid >> 1;
    const int lr = lane & 15;
    const int lcb = (lane >> 4) * 16;

    uint32_t aoff0[4], boff0[4];
    #pragma unroll
    for (int mi = 0; mi < 4; mi++)
        aoff0[mi] = swz((uint32_t)((wm * 64 + mi * 16 + lr) * 128 + lcb));
    if (TRB == 0) {
        #pragma unroll
        for (int nb = 0; nb < 4; nb++)
            boff0[nb] = 16384u + swz((uint32_t)((wn * 64 + nb * 16 + lr) * 128 + lcb));
    } else {
        // trans: lane&15 -> k-row (256B rows), lane>>4 -> 16B n sub-block
        #pragma unroll
        for (int nb = 0; nb < 4; nb++)
            boff0[nb] = 16384u + swzB((uint32_t)(lr * 256 + wn * 128 + nb * 32 + lcb));
    }

    // A: swz(base + ks*32) == swz(base) ^ (ks*32)   (bits below swizzle field)
    // B NT: same.  B NN: k advance = ks*16 rows = +ks*4096 (above swizzle field,
    //                    and (k&7) unchanged since 16 | ks*16) -> plain add.
#define LDFRAG(af, bf, sa_, ks_) do { \
        _Pragma("unroll") \
        for (int mi_ = 0; mi_ < 4; mi_++) \
            ldsm_x4((af)[mi_], (sa_) + (aoff0[mi_] ^ (uint32_t)((ks_) * 32))); \
        if (TRB == 0) { \
            _Pragma("unroll") \
            for (int nb_ = 0; nb_ < 4; nb_++) \
                ldsm_x4((bf)[nb_], (sa_) + (boff0[nb_] ^ (uint32_t)((ks_) * 32))); \
        } else { \
            _Pragma("unroll") \
            for (int nb_ = 0; nb_ < 4; nb_++) \
                ldsm_x4_t((bf)[nb_], (sa_) + boff0[nb_] + (uint32_t)((ks_) * 4096)); \
        } \
    } while (0)

    // Fragment pairing differs between NT and trans loads.
#define MMABLK(af, bf) do { \
        _Pragma("unroll") \
        for (int mi_ = 0; mi_ < 4; mi_++) \
            _Pragma("unroll") \
            for (int ni_ = 0; ni_ < 8; ni_++) { \
                uint32_t b0_ = (TRB == 0) ? (bf)[ni_ >> 1][ni_ & 1] \
                                          : (bf)[ni_ >> 1][(ni_ & 1) * 2]; \
                uint32_t b1_ = (TRB == 0) ? (bf)[ni_ >> 1][(ni_ & 1) + 2] \
                                          : (bf)[ni_ >> 1][(ni_ & 1) * 2 + 1]; \
                mma16816(acc[mi_][ni_], (af)[mi_], b0_, b1_); \
            } \
    } while (0)

    float acc[4][8][4] = {};
    uint32_t a0[4][4], b0[4][4], a1[4][4], b1[4][4];

    cp_wait1();
    __syncthreads();
    LDFRAG(a0, b0, sbase, 0);          // stage 0, ks 0

    for (int t = 0; t < T; t++) {
        const uint32_t sa = sbase + (uint32_t)(t % NSTAGE) * STG;

        LDFRAG(a1, b1, sa, 1);
        MMABLK(a0, b0);                // ks 0
        LDFRAG(a0, b0, sa, 2);
        MMABLK(a1, b1);                // ks 1
        LDFRAG(a1, b1, sa, 3);
        MMABLK(a0, b0);                // ks 2

        if (t + 2 < T) LOAD_STAGE((t + 2) % NSTAGE, t + 2);
        cp_commit();
        cp_wait1();
        __syncthreads();

        if (t + 1 < T)
            LDFRAG(a0, b0, sbase + (uint32_t)((t + 1) % NSTAGE) * STG, 0);
        MMABLK(a1, b1);                // ks 3 (covers barrier + next-stage loads)
    }

    // --- epilogue ---
    const int er = lane >> 2;
    const int ec = (lane & 3) * 2;

    if (mode == 1) {
        float* C = (float*)Cout + (size_t)bz * zC;
        #pragma unroll
        for (int mi = 0; mi < 4; mi++) {
            #pragma unroll
            for (int ni = 0; ni < 8; ni++) {
                int m0 = tile_m + wm * 64 + mi * 16 + er;
                int n0 = tile_n + wn * 64 + ni * 8 + ec;
                float* c = acc[mi][ni];
                *(float2*)(C + (size_t)m0 * ldc + n0) =
                    make_float2(c[0] * alpha, c[1] * alpha);
                *(float2*)(C + (size_t)(m0 + 8) * ldc + n0) =
                    make_float2(c[2] * alpha, c[3] * alpha);
            }
        }
    } else {
        __half* C = (__half*)Cout + (size_t)bz * zC;
        #pragma unroll
        for (int mi = 0; mi < 4; mi++) {
            #pragma unroll
            for (int ni = 0; ni < 8; ni++) {
                int m0 = tile_m + wm * 64 + mi * 16 + er;
                int n0 = tile_n + wn * 64 + ni * 8 + ec;
                float bx = 0.f, by = 0.f;
                if (mode == 0) { bx = bias[n0]; by = bias[n0 + 1]; }
                float* c = acc[mi][ni];
                *(__half2*)(C + (size_t)m0 * ldc + n0) =
                    __floats2half2_rn(c[0] * alpha + bx, c[1] * alpha + by);
                *(__half2*)(C + (size_t)(m0 + 8) * ldc + n0) =
                    __floats2half2_rn(c[2] * alpha + bx, c[3] * alpha + by);
            }
        }
    }
#undef LOAD_STAGE
#undef LDFRAG
#undef MMABLK
}

// ---------------------------------------------------------------------------
// fp32 -> fp16 conversion (vectorized)
// ---------------------------------------------------------------------------
__global__ __launch_bounds__(256)
void f2h(const float* __restrict__ in, __half* __restrict__ out, long long n4)
{
    long long i = (long long)blockIdx.x * blockDim.x + threadIdx.x;
    long long stride = (long long)gridDim.x * blockDim.x;
    for (; i < n4; i += stride) {
        float4 v = ((const float4*)in)[i];
        ((__half2*)out)[2 * i + 0] = __floats2half2_rn(v.x, v.y);
        ((__half2*)out)[2 * i + 1] = __floats2half2_rn(v.z, v.w);
    }
}

// ---------------------------------------------------------------------------
// Row softmax over fp16 scores, in place (fp32 math inside).
// ---------------------------------------------------------------------------
__global__ __launch_bounds__(256)
void softmax_rows_h(__half* __restrict__ S)
{
    const long long row = blockIdx.x;
    __half* p = S + row * (long long)SEQ;
    const int tid = threadIdx.x;
    const int lane = tid & 31;
    const int warp = tid >> 5;

    __shared__ float red_max[8];
    __shared__ float red_sum[8];

    float v[8];
    {
        uint4 raw = *(const uint4*)(p + tid * 8);
        const __half2* h = (const __half2*)&raw;
        #pragma unroll
        for (int i = 0; i < 4; i++) {
            float2 f = __half22float2(h[i]);
            v[2 * i] = f.x; v[2 * i + 1] = f.y;
        }
    }
    float m = v[0];
    #pragma unroll
    for (int i = 1; i < 8; i++) m = fmaxf(m, v[i]);
    #pragma unroll
    for (int o = 16; o > 0; o >>= 1) m = fmaxf(m, __shfl_xor_sync(0xffffffffu, m, o));
    if (lane == 0) red_max[warp] = m;
    __syncthreads();
    float mall = red_max[0];
    #pragma unroll
    for (int w = 1; w < 8; w++) mall = fmaxf(mall, red_max[w]);

    float s = 0.0f;
    #pragma unroll
    for (int i = 0; i < 8; i++) {
        v[i] = __expf(v[i] - mall);
        s += v[i];
    }
    #pragma unroll
    for (int o = 16; o > 0; o >>= 1) s += __shfl_xor_sync(0xffffffffu, s, o);
    if (lane == 0) red_sum[warp] = s;
    __syncthreads();
    float sall = 0.0f;
    #pragma unroll
    for (int w = 0; w < 8; w++) sall += red_sum[w];

    const float inv = __frcp_rn(sall);
    {
        uint4 raw;
        __half2* h = (__half2*)&raw;
        #pragma unroll
        for (int i = 0; i < 4; i++)
            h[i] = __floats2half2_rn(v[2 * i] * inv, v[2 * i + 1] * inv);
        *(uint4*)(p + tid * 8) = raw;
    }
}

// ---------------------------------------------------------------------------
// Launch
// ---------------------------------------------------------------------------
extern "C" void kernel_launch(void* const* d_in, const int* in_sizes, int n_in,
                              void* d_out, int out_size)
{
    const float* x  = (const float*)d_in[0];
    const float* W1 = (const float*)d_in[1];
    const float* b1 = (const float*)d_in[2];
    const float* W2 = (const float*)d_in[3];
    const float* b2 = (const float*)d_in[4];
    float* out = (float*)d_out;

    __half *pxh, *pWc, *pVKh, *pSh;
    float *pbc;
    cudaGetSymbolAddress((void**)&pxh,  g_xh);
    cudaGetSymbolAddress((void**)&pWc,  g_Wc);
    cudaGetSymbolAddress((void**)&pbc,  g_bc);
    cudaGetSymbolAddress((void**)&pVKh, g_VKh);
    cudaGetSymbolAddress((void**)&pSh,  g_Sh);

    const int SMEM_SZ = NSTAGE * STG;  // 98304 per CTA
    cudaFuncSetAttribute(mm_h16<0>, cudaFuncAttributeMaxDynamicSharedMemorySize, SMEM_SZ);
    cudaFuncSetAttribute(mm_h16<1>, cudaFuncAttributeMaxDynamicSharedMemorySize, SMEM_SZ);

    const float scale = 1.0f / 32.0f;  // 1/sqrt(1024)

    // 1. fp32 -> fp16 inputs; concat weights [W1;W2] and biases
    f2h<<<2048, 256>>>(x,  pxh, (long long)BATCH * SEQ * DIMD / 4);
    f2h<<<512,  256>>>(W1, pWc,                       (long long)DIMD * DIMD / 4);
    f2h<<<512,  256>>>(W2, pWc + (size_t)DIMD * DIMD, (long long)DIMD * DIMD / 4);
    cudaMemcpyAsync(pbc,        b1, DIMD * sizeof(float), cudaMemcpyDeviceToDevice);
    cudaMemcpyAsync(pbc + DIMD, b2, DIMD * sizeof(float), cudaMemcpyDeviceToDevice);

    // 2. [V | K] = fp16(x @ [W1;W2]^T + [b1;b2]) : M=16384, N=2048, K=1024 (NT)
    mm_h16<0><<<dim3(2 * DIMD / BN, BATCH * SEQ / BM, 1), 128, SMEM_SZ>>>(
        pxh, pWc, pbc, pVKh,
        DIMD, DIMD, 2 * DIMD, 0, 0, 0,
        DIMD, 1.0f, 0);

    // 3. scores[b,k,q] = fp16(scale * K[b,k,:] . V[b,q,:])  (NT)
    mm_h16<0><<<dim3(SEQ / BN, SEQ / BM, BATCH), 128, SMEM_SZ>>>(
        pVKh + DIMD, pVKh, nullptr, pSh,
        2 * DIMD, 2 * DIMD, SEQ,
        (size_t)SEQ * 2 * DIMD, (size_t)SEQ * 2 * DIMD, (size_t)SEQ * SEQ,
        DIMD, scale, 2);

    // 4. softmax in place (fp16)
    softmax_rows_h<<<BATCH * SEQ, 256>>>(pSh);

    // 5. out[b,k,d] = P[b,k,:] @ V[b,:,d]  (NN via ldsm.trans, fp32 out)
    mm_h16<1><<<dim3(DIMD / BN, SEQ / BM, BATCH), 128, SMEM_SZ>>>(
        pSh, pVKh, nullptr, out,
        SEQ, 2 * DIMD, DIMD,
        (size_t)SEQ * SEQ, (size_t)SEQ * 2 * DIMD, (size_t)SEQ * DIMD,
        SEQ, 1.0f, 1);
}

// round 10
// speedup vs baseline: 1.2721x; 1.0272x over previous
#include <cuda_runtime.h>
#include <cuda_fp16.h>
#include <cstdint>

#define DIMD  1024
#define BATCH 8
#define SEQ   2048

// ---------------------------------------------------------------------------
// Scratch (static device memory — no allocations)
// ---------------------------------------------------------------------------
__device__ __half g_xh  [(size_t)BATCH * SEQ * DIMD];      // x fp16
__device__ __half g_Wc  [(size_t)2 * DIMD * DIMD];         // [W1;W2] fp16
__device__ float  g_bc  [2 * DIMD];                        // [b1;b2] fp32
__device__ __half g_VKh [(size_t)BATCH * SEQ * 2 * DIMD];  // cols 0-1023 V(==Q), 1024-2047 K
__device__ __half g_Sh  [(size_t)BATCH * SEQ * SEQ];       // exp(scores) fp16
__device__ float  g_ps  [(size_t)BATCH * SEQ * 32];        // partial row sums
__device__ float  g_inv [(size_t)BATCH * SEQ];             // 1 / row sum

// ---------------------------------------------------------------------------
// Helpers
// ---------------------------------------------------------------------------
__device__ __forceinline__ uint32_t smem_u32(const void* p) {
    return (uint32_t)__cvta_generic_to_shared(p);
}
// SW128 swizzle for 128-byte rows: bits[6:4] ^= bits[9:7]
__device__ __forceinline__ uint32_t swz(uint32_t o) { return o ^ ((o >> 3) & 0x70); }
// swizzle for 256-byte rows: bits[6:4] ^= bits[10:8]
__device__ __forceinline__ uint32_t swzB(uint32_t o) { return o ^ ((o >> 4) & 0x70); }

__device__ __forceinline__ void cp_async16(uint32_t dst, const void* src) {
    asm volatile("cp.async.cg.shared.global [%0], [%1], 16;" :: "r"(dst), "l"(src));
}
__device__ __forceinline__ void cp_commit() {
    asm volatile("cp.async.commit_group;" ::: "memory");
}
__device__ __forceinline__ void cp_wait1() {
    asm volatile("cp.async.wait_group 1;" ::: "memory");
}
__device__ __forceinline__ void ldsm_x4(uint32_t* r, uint32_t addr) {
    asm volatile("ldmatrix.sync.aligned.m8n8.x4.shared.b16 {%0,%1,%2,%3}, [%4];"
                 : "=r"(r[0]), "=r"(r[1]), "=r"(r[2]), "=r"(r[3]) : "r"(addr));
}
__device__ __forceinline__ void ldsm_x4_t(uint32_t* r, uint32_t addr) {
    asm volatile("ldmatrix.sync.aligned.m8n8.x4.trans.shared.b16 {%0,%1,%2,%3}, [%4];"
                 : "=r"(r[0]), "=r"(r[1]), "=r"(r[2]), "=r"(r[3]) : "r"(addr));
}
__device__ __forceinline__ void mma16816(float* c, const uint32_t* a,
                                         uint32_t b0, uint32_t b1) {
    asm volatile("mma.sync.aligned.m16n8k16.row.col.f32.f16.f16.f32 "
                 "{%0,%1,%2,%3}, {%4,%5,%6,%7}, {%8,%9}, {%0,%1,%2,%3};"
                 : "+f"(c[0]), "+f"(c[1]), "+f"(c[2]), "+f"(c[3])
                 : "r"(a[0]), "r"(a[1]), "r"(a[2]), "r"(a[3]), "r"(b0), "r"(b1));
}

// ---------------------------------------------------------------------------
// fp16 tensor-core GEMM, templated on B layout:
//   TRB=0 (NT): C = alpha * A[M,K] @ B[N,K]^T
//   TRB=1 (NN): C = alpha * A[M,K] @ B[K,N]   (ldsm.trans)
// Block tile 128x128, BK=64, 3-stage cp.async ring, 128 threads (4 warps 2x2),
// warp tile 64x64, 2 CTAs/SM, register double-buffering.
// mode 0: half out + fp32 bias(col).   mode 1: float out.   mode 2: half out.
// mode 3: half out = exp(alpha*acc), partial row sums -> g_ps[row*32 + bx*2+wn].
// mode 4: float out * rowinv (aux = inv, row-global index).
// ---------------------------------------------------------------------------
#define BM 128
#define BN 128
#define BKH 64
#define STG 32768
#define NSTAGE 3

template<int TRB>
__global__ __launch_bounds__(128, 2)
void mm_h16(const __half* __restrict__ A, const __half* __restrict__ B,
            const float* __restrict__ aux, void* __restrict__ Cout,
            int lda, int ldb, int ldc,
            size_t zA, size_t zB, size_t zC,
            int K, float alpha, int mode)
{
    extern __shared__ char smem[];
    const uint32_t sbase = smem_u32(smem);
    const int tid = threadIdx.x;
    const int wid = tid >> 5;
    const int lane = tid & 31;

    const int bz = blockIdx.z;
    A += (size_t)bz * zA;
    B += (size_t)bz * zB;

    const int tile_m = blockIdx.y * BM;
    const int tile_n = blockIdx.x * BN;
    const int T = K / BKH;

    // --- A loader: 8 x 16B chunks per thread ---
    const int rA = tid >> 3;
    const int kcA = tid & 7;
    const __half* gA = A + (size_t)(tile_m + rA) * lda + kcA * 8;
    const uint32_t dA = swz((uint32_t)(rA * 128 + kcA * 16));

    // --- B loader ---
    const __half* gB;
    uint32_t dB;
    if (TRB == 0) {
        gB = B + (size_t)(tile_n + rA) * ldb + kcA * 8;
        dB = 16384u + swz((uint32_t)(rA * 128 + kcA * 16));
    } else {
        const int rB = tid >> 4;
        const int cB = tid & 15;
        gB = B + (size_t)rB * ldb + tile_n + cB * 8;
        dB = 16384u + swzB((uint32_t)(rB * 256 + cB * 16));
    }

#define LOAD_STAGE(s, t) do { \
        uint32_t sb_ = sbase + (uint32_t)(s) * STG; \
        const __half* pa_ = gA + (size_t)(t) * BKH; \
        _Pragma("unroll") \
        for (int i_ = 0; i_ < 8; i_++) \
            cp_async16(sb_ + dA + i_ * 2048u, pa_ + (size_t)(16 * i_) * lda); \
        if (TRB == 0) { \
            const __half* pb_ = gB + (size_t)(t) * BKH; \
            _Pragma("unroll") \
            for (int i_ = 0; i_ < 8; i_++) \
                cp_async16(sb_ + dB + i_ * 2048u, pb_ + (size_t)(16 * i_) * ldb); \
        } else { \
            const __half* pb_ = gB + (size_t)(t) * BKH * ldb; \
            _Pragma("unroll") \
            for (int i_ = 0; i_ < 8; i_++) \
                cp_async16(sb_ + dB + i_ * 2048u, pb_ + (size_t)(8 * i_) * ldb); \
        } \
    } while (0)

    #pragma unroll
    for (int p = 0; p < 2; p++) {
        if (p < T) LOAD_STAGE(p, p);
        cp_commit();
    }

    // --- compute plan ---
    const int wm = wid & 1;
    const int wn = wid >> 1;
    const int lr = lane & 15;
    const int lcb = (lane >> 4) * 16;

    uint32_t aoff0[4], boff0[4];
    #pragma unroll
    for (int mi = 0; mi < 4; mi++)
        aoff0[mi] = swz((uint32_t)((wm * 64 + mi * 16 + lr) * 128 + lcb));
    if (TRB == 0) {
        #pragma unroll
        for (int nb = 0; nb < 4; nb++)
            boff0[nb] = 16384u + swz((uint32_t)((wn * 64 + nb * 16 + lr) * 128 + lcb));
    } else {
        #pragma unroll
        for (int nb = 0; nb < 4; nb++)
            boff0[nb] = 16384u + swzB((uint32_t)(lr * 256 + wn * 128 + nb * 32 + lcb));
    }

#define LDFRAG(af, bf, sa_, ks_) do { \
        _Pragma("unroll") \
        for (int mi_ = 0; mi_ < 4; mi_++) \
            ldsm_x4((af)[mi_], (sa_) + (aoff0[mi_] ^ (uint32_t)((ks_) * 32))); \
        if (TRB == 0) { \
            _Pragma("unroll") \
            for (int nb_ = 0; nb_ < 4; nb_++) \
                ldsm_x4((bf)[nb_], (sa_) + (boff0[nb_] ^ (uint32_t)((ks_) * 32))); \
        } else { \
            _Pragma("unroll") \
            for (int nb_ = 0; nb_ < 4; nb_++) \
                ldsm_x4_t((bf)[nb_], (sa_) + boff0[nb_] + (uint32_t)((ks_) * 4096)); \
        } \
    } while (0)

#define MMABLK(af, bf) do { \
        _Pragma("unroll") \
        for (int mi_ = 0; mi_ < 4; mi_++) \
            _Pragma("unroll") \
            for (int ni_ = 0; ni_ < 8; ni_++) { \
                uint32_t b0_ = (TRB == 0) ? (bf)[ni_ >> 1][ni_ & 1] \
                                          : (bf)[ni_ >> 1][(ni_ & 1) * 2]; \
                uint32_t b1_ = (TRB == 0) ? (bf)[ni_ >> 1][(ni_ & 1) + 2] \
                                          : (bf)[ni_ >> 1][(ni_ & 1) * 2 + 1]; \
                mma16816(acc[mi_][ni_], (af)[mi_], b0_, b1_); \
            } \
    } while (0)

    float acc[4][8][4] = {};
    uint32_t a0[4][4], b0[4][4], a1[4][4], b1[4][4];

    cp_wait1();
    __syncthreads();
    LDFRAG(a0, b0, sbase, 0);

    for (int t = 0; t < T; t++) {
        const uint32_t sa = sbase + (uint32_t)(t % NSTAGE) * STG;

        LDFRAG(a1, b1, sa, 1);
        MMABLK(a0, b0);
        LDFRAG(a0, b0, sa, 2);
        MMABLK(a1, b1);
        LDFRAG(a1, b1, sa, 3);
        MMABLK(a0, b0);

        if (t + 2 < T) LOAD_STAGE((t + 2) % NSTAGE, t + 2);
        cp_commit();
        cp_wait1();
        __syncthreads();

        if (t + 1 < T)
            LDFRAG(a0, b0, sbase + (uint32_t)((t + 1) % NSTAGE) * STG, 0);
        MMABLK(a1, b1);
    }

    // --- epilogue ---
    const int er = lane >> 2;
    const int ec = (lane & 3) * 2;

    if (mode == 1 || mode == 4) {
        float* C = (float*)Cout + (size_t)bz * zC;
        const float* rinv = aux + (size_t)bz * SEQ;
        #pragma unroll
        for (int mi = 0; mi < 4; mi++) {
            int m0 = tile_m + wm * 64 + mi * 16 + er;
            float s0 = alpha, s1 = alpha;
            if (mode == 4) { s0 = rinv[m0]; s1 = rinv[m0 + 8]; }
            #pragma unroll
            for (int ni = 0; ni < 8; ni++) {
                int n0 = tile_n + wn * 64 + ni * 8 + ec;
                float* c = acc[mi][ni];
                *(float2*)(C + (size_t)m0 * ldc + n0) =
                    make_float2(c[0] * s0, c[1] * s0);
                *(float2*)(C + (size_t)(m0 + 8) * ldc + n0) =
                    make_float2(c[2] * s1, c[3] * s1);
            }
        }
    } else {
        __half* C = (__half*)Cout + (size_t)bz * zC;
        float psum[4][2];
        #pragma unroll
        for (int mi = 0; mi < 4; mi++) { psum[mi][0] = 0.f; psum[mi][1] = 0.f; }

        #pragma unroll
        for (int mi = 0; mi < 4; mi++) {
            #pragma unroll
            for (int ni = 0; ni < 8; ni++) {
                int m0 = tile_m + wm * 64 + mi * 16 + er;
                int n0 = tile_n + wn * 64 + ni * 8 + ec;
                float* c = acc[mi][ni];
                __half2 h01, h23;
                if (mode == 3) {
                    h01 = __floats2half2_rn(__expf(c[0] * alpha), __expf(c[1] * alpha));
                    h23 = __floats2half2_rn(__expf(c[2] * alpha), __expf(c[3] * alpha));
                    float2 f01 = __half22float2(h01);
                    float2 f23 = __half22float2(h23);
                    psum[mi][0] += f01.x + f01.y;
                    psum[mi][1] += f23.x + f23.y;
                } else {
                    float bx = 0.f, by = 0.f;
                    if (mode == 0) { bx = aux[n0]; by = aux[n0 + 1]; }
                    h01 = __floats2half2_rn(c[0] * alpha + bx, c[1] * alpha + by);
                    h23 = __floats2half2_rn(c[2] * alpha + bx, c[3] * alpha + by);
                }
                *(__half2*)(C + (size_t)m0 * ldc + n0) = h01;
                *(__half2*)(C + (size_t)(m0 + 8) * ldc + n0) = h23;
            }
        }

        if (mode == 3) {
            #pragma unroll
            for (int mi = 0; mi < 4; mi++) {
                #pragma unroll
                for (int h = 0; h < 2; h++) {
                    float v = psum[mi][h];
                    v += __shfl_xor_sync(0xffffffffu, v, 1);
                    v += __shfl_xor_sync(0xffffffffu, v, 2);
                    if ((lane & 3) == 0) {
                        int row = bz * SEQ + tile_m + wm * 64 + mi * 16 + er + h * 8;
                        g_ps[(size_t)row * 32 + blockIdx.x * 2 + wn] = v;
                    }
                }
            }
        }
    }
#undef LOAD_STAGE
#undef LDFRAG
#undef MMABLK
}

// ---------------------------------------------------------------------------
// fp32 -> fp16 conversion (vectorized)
// ---------------------------------------------------------------------------
__global__ __launch_bounds__(256)
void f2h(const float* __restrict__ in, __half* __restrict__ out, long long n4)
{
    long long i = (long long)blockIdx.x * blockDim.x + threadIdx.x;
    long long stride = (long long)gridDim.x * blockDim.x;
    for (; i < n4; i += stride) {
        float4 v = ((const float4*)in)[i];
        ((__half2*)out)[2 * i + 0] = __floats2half2_rn(v.x, v.y);
        ((__half2*)out)[2 * i + 1] = __floats2half2_rn(v.z, v.w);
    }
}

// ---------------------------------------------------------------------------
// Weight/bias prep: Wc = fp16([W1;W2]), bc = [b1;b2]
// ---------------------------------------------------------------------------
__global__ __launch_bounds__(256)
void prep_wb(const float* __restrict__ W1, const float* __restrict__ W2,
             const float* __restrict__ b1, const float* __restrict__ b2,
             __half* __restrict__ Wc, float* __restrict__ bc)
{
    const long long n4 = (long long)DIMD * DIMD / 4;  // float4 per weight matrix
    long long i = (long long)blockIdx.x * blockDim.x + threadIdx.x;
    long long stride = (long long)gridDim.x * blockDim.x;
    for (long long j = i; j < 2 * n4; j += stride) {
        const float* src = (j < n4) ? W1 : W2;
        long long k = (j < n4) ? j : j - n4;
        float4 v = ((const float4*)src)[k];
        ((__half2*)Wc)[2 * j + 0] = __floats2half2_rn(v.x, v.y);
        ((__half2*)Wc)[2 * j + 1] = __floats2half2_rn(v.z, v.w);
    }
    for (long long j = i; j < 2 * DIMD; j += stride)
        bc[j] = (j < DIMD) ? b1[j] : b2[j - DIMD];
}

// ---------------------------------------------------------------------------
// Finalize: inv[row] = 1 / sum(partials[row][0..31])
// ---------------------------------------------------------------------------
__global__ __launch_bounds__(256)
void finalize_inv(const float* __restrict__ ps, float* __restrict__ inv)
{
    int row = blockIdx.x * blockDim.x + threadIdx.x;
    if (row >= BATCH * SEQ) return;
    const float* p = ps + (size_t)row * 32;
    float s = 0.f;
    #pragma unroll
    for (int i = 0; i < 32; i++) s += p[i];
    inv[row] = 1.0f / s;
}

// ---------------------------------------------------------------------------
// Launch
// ---------------------------------------------------------------------------
extern "C" void kernel_launch(void* const* d_in, const int* in_sizes, int n_in,
                              void* d_out, int out_size)
{
    const float* x  = (const float*)d_in[0];
    const float* W1 = (const float*)d_in[1];
    const float* b1 = (const float*)d_in[2];
    const float* W2 = (const float*)d_in[3];
    const float* b2 = (const float*)d_in[4];
    float* out = (float*)d_out;

    __half *pxh, *pWc, *pVKh, *pSh;
    float *pbc, *pps, *pinv;
    cudaGetSymbolAddress((void**)&pxh,  g_xh);
    cudaGetSymbolAddress((void**)&pWc,  g_Wc);
    cudaGetSymbolAddress((void**)&pbc,  g_bc);
    cudaGetSymbolAddress((void**)&pVKh, g_VKh);
    cudaGetSymbolAddress((void**)&pSh,  g_Sh);
    cudaGetSymbolAddress((void**)&pps,  g_ps);
    cudaGetSymbolAddress((void**)&pinv, g_inv);

    const int SMEM_SZ = NSTAGE * STG;  // 98304 per CTA
    cudaFuncSetAttribute(mm_h16<0>, cudaFuncAttributeMaxDynamicSharedMemorySize, SMEM_SZ);
    cudaFuncSetAttribute(mm_h16<1>, cudaFuncAttributeMaxDynamicSharedMemorySize, SMEM_SZ);

    const float scale = 1.0f / 32.0f;  // 1/sqrt(1024)

    // 1. fp32 -> fp16 inputs and weights/biases
    f2h<<<2048, 256>>>(x, pxh, (long long)BATCH * SEQ * DIMD / 4);
    prep_wb<<<1024, 256>>>(W1, W2, b1, b2, pWc, pbc);

    // 2. [V | K] = fp16(x @ [W1;W2]^T + [b1;b2]) : M=16384, N=2048, K=1024 (NT)
    mm_h16<0><<<dim3(2 * DIMD / BN, BATCH * SEQ / BM, 1), 128, SMEM_SZ>>>(
        pxh, pWc, pbc, pVKh,
        DIMD, DIMD, 2 * DIMD, 0, 0, 0,
        DIMD, 1.0f, 0);

    // 3. P = fp16(exp(scale * K . V)) + partial row sums (NT, mode 3)
    mm_h16<0><<<dim3(SEQ / BN, SEQ / BM, BATCH), 128, SMEM_SZ>>>(
        pVKh + DIMD, pVKh, nullptr, pSh,
        2 * DIMD, 2 * DIMD, SEQ,
        (size_t)SEQ * 2 * DIMD, (size_t)SEQ * 2 * DIMD, (size_t)SEQ * SEQ,
        DIMD, scale, 3);

    // 4. inv[row] = 1 / rowsum
    finalize_inv<<<(BATCH * SEQ + 255) / 256, 256>>>(pps, pinv);

    // 5. out = inv[row] * (P @ V)  (NN via ldsm.trans, fp32 out, mode 4)
    mm_h16<1><<<dim3(DIMD / BN, SEQ / BM, BATCH), 128, SMEM_SZ>>>(
        pSh, pVKh, pinv, out,
        SEQ, 2 * DIMD, DIMD,
        (size_t)SEQ * SEQ, (size_t)SEQ * 2 * DIMD, (size_t)SEQ * DIMD,
        SEQ, 1.0f, 4);
}

// round 11
// speedup vs baseline: 1.2859x; 1.0108x over previous
#include <cuda_runtime.h>
#include <cuda_fp16.h>
#include <cstdint>

#define DIMD  1024
#define BATCH 8
#define SEQ   2048

// ---------------------------------------------------------------------------
// Scratch (static device memory — no allocations)
// ---------------------------------------------------------------------------
__device__ __half g_xh  [(size_t)BATCH * SEQ * DIMD];      // x fp16
__device__ __half g_Wc  [(size_t)2 * DIMD * DIMD];         // [W1;W2] fp16
__device__ float  g_bc  [2 * DIMD];                        // [b1;b2] fp32
__device__ __half g_VKh [(size_t)BATCH * SEQ * 2 * DIMD];  // cols 0-1023 V(==Q), 1024-2047 K
__device__ __half g_Sh  [(size_t)BATCH * SEQ * SEQ];       // exp(scores) fp16
__device__ float  g_ps  [(size_t)BATCH * SEQ * 32];        // partial row sums
__device__ float  g_inv [(size_t)BATCH * SEQ];             // 1 / row sum

// ---------------------------------------------------------------------------
// Helpers
// ---------------------------------------------------------------------------
__device__ __forceinline__ uint32_t smem_u32(const void* p) {
    return (uint32_t)__cvta_generic_to_shared(p);
}
// SW128 swizzle for 128-byte rows: bits[6:4] ^= bits[9:7]
__device__ __forceinline__ uint32_t swz(uint32_t o) { return o ^ ((o >> 3) & 0x70); }
// swizzle for 256-byte rows: bits[6:4] ^= bits[10:8]
__device__ __forceinline__ uint32_t swzB(uint32_t o) { return o ^ ((o >> 4) & 0x70); }

__device__ __forceinline__ void cp_async16(uint32_t dst, const void* src) {
    asm volatile("cp.async.cg.shared.global [%0], [%1], 16;" :: "r"(dst), "l"(src));
}
__device__ __forceinline__ void cp_commit() {
    asm volatile("cp.async.commit_group;" ::: "memory");
}
__device__ __forceinline__ void cp_wait1() {
    asm volatile("cp.async.wait_group 1;" ::: "memory");
}
__device__ __forceinline__ void ldsm_x4(uint32_t* r, uint32_t addr) {
    asm volatile("ldmatrix.sync.aligned.m8n8.x4.shared.b16 {%0,%1,%2,%3}, [%4];"
                 : "=r"(r[0]), "=r"(r[1]), "=r"(r[2]), "=r"(r[3]) : "r"(addr));
}
__device__ __forceinline__ void ldsm_x4_t(uint32_t* r, uint32_t addr) {
    asm volatile("ldmatrix.sync.aligned.m8n8.x4.trans.shared.b16 {%0,%1,%2,%3}, [%4];"
                 : "=r"(r[0]), "=r"(r[1]), "=r"(r[2]), "=r"(r[3]) : "r"(addr));
}
__device__ __forceinline__ void mma16816(float* c, const uint32_t* a,
                                         uint32_t b0, uint32_t b1) {
    asm volatile("mma.sync.aligned.m16n8k16.row.col.f32.f16.f16.f32 "
                 "{%0,%1,%2,%3}, {%4,%5,%6,%7}, {%8,%9}, {%0,%1,%2,%3};"
                 : "+f"(c[0]), "+f"(c[1]), "+f"(c[2]), "+f"(c[3])
                 : "r"(a[0]), "r"(a[1]), "r"(a[2]), "r"(a[3]), "r"(b0), "r"(b1));
}
// exp(x) for two halfs at once: ex2.approx.f16x2 (inputs pre-scaled by log2e)
__device__ __forceinline__ __half2 h2_ex2(__half2 x) {
    __half2 r;
    asm("ex2.approx.f16x2 %0, %1;" : "=r"(*(uint32_t*)&r) : "r"(*(const uint32_t*)&x));
    return r;
}

// ---------------------------------------------------------------------------
// fp16 tensor-core GEMM, templated on B layout:
//   TRB=0 (NT): C = alpha * A[M,K] @ B[N,K]^T
//   TRB=1 (NN): C = alpha * A[M,K] @ B[K,N]   (ldsm.trans)
// Block tile 128x128, BK=64, 3-stage cp.async ring, 128 threads (4 warps 2x2),
// warp tile 64x64, 2 CTAs/SM, register double-buffering.
// mode 0: half out + fp32 bias(col).   mode 1: float out.   mode 2: half out.
// mode 3: half out = exp(alpha*acc) via f16x2 ex2, psums -> g_ps[row*32+bx*2+wn].
// mode 4: float out * rowinv (aux = inv, row-global index).
// ---------------------------------------------------------------------------
#define BM 128
#define BN 128
#define BKH 64
#define STG 32768
#define NSTAGE 3

template<int TRB>
__global__ __launch_bounds__(128, 2)
void mm_h16(const __half* __restrict__ A, const __half* __restrict__ B,
            const float* __restrict__ aux, void* __restrict__ Cout,
            int lda, int ldb, int ldc,
            size_t zA, size_t zB, size_t zC,
            int K, float alpha, int mode)
{
    extern __shared__ char smem[];
    const uint32_t sbase = smem_u32(smem);
    const int tid = threadIdx.x;
    const int wid = tid >> 5;
    const int lane = tid & 31;

    const int bz = blockIdx.z;
    A += (size_t)bz * zA;
    B += (size_t)bz * zB;

    const int tile_m = blockIdx.y * BM;
    const int tile_n = blockIdx.x * BN;
    const int T = K / BKH;

    // --- A loader: 8 x 16B chunks per thread ---
    const int rA = tid >> 3;
    const int kcA = tid & 7;
    const __half* gA = A + (size_t)(tile_m + rA) * lda + kcA * 8;
    const uint32_t dA = swz((uint32_t)(rA * 128 + kcA * 16));

    // --- B loader ---
    const __half* gB;
    uint32_t dB;
    if (TRB == 0) {
        gB = B + (size_t)(tile_n + rA) * ldb + kcA * 8;
        dB = 16384u + swz((uint32_t)(rA * 128 + kcA * 16));
    } else {
        const int rB = tid >> 4;
        const int cB = tid & 15;
        gB = B + (size_t)rB * ldb + tile_n + cB * 8;
        dB = 16384u + swzB((uint32_t)(rB * 256 + cB * 16));
    }

#define LOAD_STAGE(s, t) do { \
        uint32_t sb_ = sbase + (uint32_t)(s) * STG; \
        const __half* pa_ = gA + (size_t)(t) * BKH; \
        _Pragma("unroll") \
        for (int i_ = 0; i_ < 8; i_++) \
            cp_async16(sb_ + dA + i_ * 2048u, pa_ + (size_t)(16 * i_) * lda); \
        if (TRB == 0) { \
            const __half* pb_ = gB + (size_t)(t) * BKH; \
            _Pragma("unroll") \
            for (int i_ = 0; i_ < 8; i_++) \
                cp_async16(sb_ + dB + i_ * 2048u, pb_ + (size_t)(16 * i_) * ldb); \
        } else { \
            const __half* pb_ = gB + (size_t)(t) * BKH * ldb; \
            _Pragma("unroll") \
            for (int i_ = 0; i_ < 8; i_++) \
                cp_async16(sb_ + dB + i_ * 2048u, pb_ + (size_t)(8 * i_) * ldb); \
        } \
    } while (0)

    #pragma unroll
    for (int p = 0; p < 2; p++) {
        if (p < T) LOAD_STAGE(p, p);
        cp_commit();
    }

    // --- compute plan ---
    const int wm = wid & 1;
    const int wn = wid >> 1;
    const int lr = lane & 15;
    const int lcb = (lane >> 4) * 16;

    uint32_t aoff0[4], boff0[4];
    #pragma unroll
    for (int mi = 0; mi < 4; mi++)
        aoff0[mi] = swz((uint32_t)((wm * 64 + mi * 16 + lr) * 128 + lcb));
    if (TRB == 0) {
        #pragma unroll
        for (int nb = 0; nb < 4; nb++)
            boff0[nb] = 16384u + swz((uint32_t)((wn * 64 + nb * 16 + lr) * 128 + lcb));
    } else {
        #pragma unroll
        for (int nb = 0; nb < 4; nb++)
            boff0[nb] = 16384u + swzB((uint32_t)(lr * 256 + wn * 128 + nb * 32 + lcb));
    }

#define LDFRAG(af, bf, sa_, ks_) do { \
        _Pragma("unroll") \
        for (int mi_ = 0; mi_ < 4; mi_++) \
            ldsm_x4((af)[mi_], (sa_) + (aoff0[mi_] ^ (uint32_t)((ks_) * 32))); \
        if (TRB == 0) { \
            _Pragma("unroll") \
            for (int nb_ = 0; nb_ < 4; nb_++) \
                ldsm_x4((bf)[nb_], (sa_) + (boff0[nb_] ^ (uint32_t)((ks_) * 32))); \
        } else { \
            _Pragma("unroll") \
            for (int nb_ = 0; nb_ < 4; nb_++) \
                ldsm_x4_t((bf)[nb_], (sa_) + boff0[nb_] + (uint32_t)((ks_) * 4096)); \
        } \
    } while (0)

#define MMABLK(af, bf) do { \
        _Pragma("unroll") \
        for (int mi_ = 0; mi_ < 4; mi_++) \
            _Pragma("unroll") \
            for (int ni_ = 0; ni_ < 8; ni_++) { \
                uint32_t b0_ = (TRB == 0) ? (bf)[ni_ >> 1][ni_ & 1] \
                                          : (bf)[ni_ >> 1][(ni_ & 1) * 2]; \
                uint32_t b1_ = (TRB == 0) ? (bf)[ni_ >> 1][(ni_ & 1) + 2] \
                                          : (bf)[ni_ >> 1][(ni_ & 1) * 2 + 1]; \
                mma16816(acc[mi_][ni_], (af)[mi_], b0_, b1_); \
            } \
    } while (0)

    float acc[4][8][4] = {};
    uint32_t a0[4][4], b0[4][4], a1[4][4], b1[4][4];

    cp_wait1();
    __syncthreads();
    LDFRAG(a0, b0, sbase, 0);

    for (int t = 0; t < T; t++) {
        const uint32_t sa = sbase + (uint32_t)(t % NSTAGE) * STG;

        LDFRAG(a1, b1, sa, 1);
        MMABLK(a0, b0);
        LDFRAG(a0, b0, sa, 2);
        MMABLK(a1, b1);
        LDFRAG(a1, b1, sa, 3);
        MMABLK(a0, b0);

        if (t + 2 < T) LOAD_STAGE((t + 2) % NSTAGE, t + 2);
        cp_commit();
        cp_wait1();
        __syncthreads();

        if (t + 1 < T)
            LDFRAG(a0, b0, sbase + (uint32_t)((t + 1) % NSTAGE) * STG, 0);
        MMABLK(a1, b1);
    }

    // --- epilogue ---
    const int er = lane >> 2;
    const int ec = (lane & 3) * 2;

    if (mode == 1 || mode == 4) {
        float* C = (float*)Cout + (size_t)bz * zC;
        const float* rinv = aux + (size_t)bz * SEQ;
        #pragma unroll
        for (int mi = 0; mi < 4; mi++) {
            int m0 = tile_m + wm * 64 + mi * 16 + er;
            float s0 = alpha, s1 = alpha;
            if (mode == 4) { s0 = rinv[m0]; s1 = rinv[m0 + 8]; }
            #pragma unroll
            for (int ni = 0; ni < 8; ni++) {
                int n0 = tile_n + wn * 64 + ni * 8 + ec;
                float* c = acc[mi][ni];
                *(float2*)(C + (size_t)m0 * ldc + n0) =
                    make_float2(c[0] * s0, c[1] * s0);
                *(float2*)(C + (size_t)(m0 + 8) * ldc + n0) =
                    make_float2(c[2] * s1, c[3] * s1);
            }
        }
    } else {
        __half* C = (__half*)Cout + (size_t)bz * zC;
        float psum[4][2];
        #pragma unroll
        for (int mi = 0; mi < 4; mi++) { psum[mi][0] = 0.f; psum[mi][1] = 0.f; }

        const float l2e_alpha = alpha * 1.4426950408889634f;  // alpha * log2(e)

        #pragma unroll
        for (int mi = 0; mi < 4; mi++) {
            #pragma unroll
            for (int ni = 0; ni < 8; ni++) {
                int m0 = tile_m + wm * 64 + mi * 16 + er;
                int n0 = tile_n + wn * 64 + ni * 8 + ec;
                float* c = acc[mi][ni];
                __half2 h01, h23;
                if (mode == 3) {
                    // exp(alpha*c) = 2^(alpha*log2e*c), computed in f16x2
                    h01 = h2_ex2(__floats2half2_rn(c[0] * l2e_alpha, c[1] * l2e_alpha));
                    h23 = h2_ex2(__floats2half2_rn(c[2] * l2e_alpha, c[3] * l2e_alpha));
                    float2 f01 = __half22float2(h01);
                    float2 f23 = __half22float2(h23);
                    psum[mi][0] += f01.x + f01.y;
                    psum[mi][1] += f23.x + f23.y;
                } else {
                    float bx = 0.f, by = 0.f;
                    if (mode == 0) { bx = aux[n0]; by = aux[n0 + 1]; }
                    h01 = __floats2half2_rn(c[0] * alpha + bx, c[1] * alpha + by);
                    h23 = __floats2half2_rn(c[2] * alpha + bx, c[3] * alpha + by);
                }
                *(__half2*)(C + (size_t)m0 * ldc + n0) = h01;
                *(__half2*)(C + (size_t)(m0 + 8) * ldc + n0) = h23;
            }
        }

        if (mode == 3) {
            #pragma unroll
            for (int mi = 0; mi < 4; mi++) {
                #pragma unroll
                for (int h = 0; h < 2; h++) {
                    float v = psum[mi][h];
                    v += __shfl_xor_sync(0xffffffffu, v, 1);
                    v += __shfl_xor_sync(0xffffffffu, v, 2);
                    if ((lane & 3) == 0) {
                        int row = bz * SEQ + tile_m + wm * 64 + mi * 16 + er + h * 8;
                        g_ps[(size_t)row * 32 + blockIdx.x * 2 + wn] = v;
                    }
                }
            }
        }
    }
#undef LOAD_STAGE
#undef LDFRAG
#undef MMABLK
}

// ---------------------------------------------------------------------------
// Combined prep: xh = fp16(x), Wc = fp16([W1;W2]), bc = [b1;b2]
// ---------------------------------------------------------------------------
__global__ __launch_bounds__(256)
void prep_all(const float* __restrict__ x,
              const float* __restrict__ W1, const float* __restrict__ W2,
              const float* __restrict__ b1, const float* __restrict__ b2,
              __half* __restrict__ xh, __half* __restrict__ Wc,
              float* __restrict__ bc)
{
    const long long nx4 = (long long)BATCH * SEQ * DIMD / 4;
    const long long nw4 = (long long)DIMD * DIMD / 4;
    long long i = (long long)blockIdx.x * blockDim.x + threadIdx.x;
    long long stride = (long long)gridDim.x * blockDim.x;

    for (long long j = i; j < nx4; j += stride) {
        float4 v = ((const float4*)x)[j];
        ((__half2*)xh)[2 * j + 0] = __floats2half2_rn(v.x, v.y);
        ((__half2*)xh)[2 * j + 1] = __floats2half2_rn(v.z, v.w);
    }
    for (long long j = i; j < 2 * nw4; j += stride) {
        const float* src = (j < nw4) ? W1 : W2;
        long long k = (j < nw4) ? j : j - nw4;
        float4 v = ((const float4*)src)[k];
        ((__half2*)Wc)[2 * j + 0] = __floats2half2_rn(v.x, v.y);
        ((__half2*)Wc)[2 * j + 1] = __floats2half2_rn(v.z, v.w);
    }
    for (long long j = i; j < 2 * DIMD; j += stride)
        bc[j] = (j < DIMD) ? b1[j] : b2[j - DIMD];
}

// ---------------------------------------------------------------------------
// Finalize: inv[row] = 1 / sum(partials[row][0..31])
// ---------------------------------------------------------------------------
__global__ __launch_bounds__(256)
void finalize_inv(const float* __restrict__ ps, float* __restrict__ inv)
{
    int row = blockIdx.x * blockDim.x + threadIdx.x;
    if (row >= BATCH * SEQ) return;
    const float* p = ps + (size_t)row * 32;
    float s = 0.f;
    #pragma unroll
    for (int i = 0; i < 32; i++) s += p[i];
    inv[row] = 1.0f / s;
}

// ---------------------------------------------------------------------------
// Launch
// ---------------------------------------------------------------------------
extern "C" void kernel_launch(void* const* d_in, const int* in_sizes, int n_in,
                              void* d_out, int out_size)
{
    const float* x  = (const float*)d_in[0];
    const float* W1 = (const float*)d_in[1];
    const float* b1 = (const float*)d_in[2];
    const float* W2 = (const float*)d_in[3];
    const float* b2 = (const float*)d_in[4];
    float* out = (float*)d_out;

    __half *pxh, *pWc, *pVKh, *pSh;
    float *pbc, *pps, *pinv;
    cudaGetSymbolAddress((void**)&pxh,  g_xh);
    cudaGetSymbolAddress((void**)&pWc,  g_Wc);
    cudaGetSymbolAddress((void**)&pbc,  g_bc);
    cudaGetSymbolAddress((void**)&pVKh, g_VKh);
    cudaGetSymbolAddress((void**)&pSh,  g_Sh);
    cudaGetSymbolAddress((void**)&pps,  g_ps);
    cudaGetSymbolAddress((void**)&pinv, g_inv);

    const int SMEM_SZ = NSTAGE * STG;  // 98304 per CTA
    cudaFuncSetAttribute(mm_h16<0>, cudaFuncAttributeMaxDynamicSharedMemorySize, SMEM_SZ);
    cudaFuncSetAttribute(mm_h16<1>, cudaFuncAttributeMaxDynamicSharedMemorySize, SMEM_SZ);

    const float scale = 1.0f / 32.0f;  // 1/sqrt(1024)

    // 1. fp32 -> fp16 inputs/weights/biases (one kernel)
    prep_all<<<2048, 256>>>(x, W1, W2, b1, b2, pxh, pWc, pbc);

    // 2. [V | K] = fp16(x @ [W1;W2]^T + [b1;b2]) : M=16384, N=2048, K=1024 (NT)
    mm_h16<0><<<dim3(2 * DIMD / BN, BATCH * SEQ / BM, 1), 128, SMEM_SZ>>>(
        pxh, pWc, pbc, pVKh,
        DIMD, DIMD, 2 * DIMD, 0, 0, 0,
        DIMD, 1.0f, 0);

    // 3. P = fp16(exp(scale * K . V)) + partial row sums (NT, mode 3)
    mm_h16<0><<<dim3(SEQ / BN, SEQ / BM, BATCH), 128, SMEM_SZ>>>(
        pVKh + DIMD, pVKh, nullptr, pSh,
        2 * DIMD, 2 * DIMD, SEQ,
        (size_t)SEQ * 2 * DIMD, (size_t)SEQ * 2 * DIMD, (size_t)SEQ * SEQ,
        DIMD, scale, 3);

    // 4. inv[row] = 1 / rowsum
    finalize_inv<<<(BATCH * SEQ + 255) / 256, 256>>>(pps, pinv);

    // 5. out = inv[row] * (P @ V)  (NN via ldsm.trans, fp32 out, mode 4)
    mm_h16<1><<<dim3(DIMD / BN, SEQ / BM, BATCH), 128, SMEM_SZ>>>(
        pSh, pVKh, pinv, out,
        SEQ, 2 * DIMD, DIMD,
        (size_t)SEQ * SEQ, (size_t)SEQ * 2 * DIMD, (size_t)SEQ * DIMD,
        SEQ, 1.0f, 4);
}

// round 12
// speedup vs baseline: 1.3631x; 1.0601x over previous
#include <cuda_runtime.h>
#include <cuda_fp16.h>
#include <cstdint>

#define DIMD  1024
#define BATCH 8
#define SEQ   2048

// ---------------------------------------------------------------------------
// Scratch (static device memory — no allocations)
// ---------------------------------------------------------------------------
__device__ __half g_xh  [(size_t)BATCH * SEQ * DIMD];      // x fp16
__device__ __half g_Wc  [(size_t)2 * DIMD * DIMD];         // [W1;W2] fp16
__device__ float  g_bc  [2 * DIMD];                        // [b1;b2] fp32
__device__ __half g_VKh [(size_t)BATCH * SEQ * 2 * DIMD];  // cols 0-1023 V(==Q), 1024-2047 K
__device__ __half g_Sh  [(size_t)BATCH * SEQ * SEQ];       // exp(scores) fp16
__device__ float  g_ps  [(size_t)BATCH * SEQ * 32];        // partial row sums
__device__ float  g_inv [(size_t)BATCH * SEQ];             // 1 / row sum

// ---------------------------------------------------------------------------
// Helpers
// ---------------------------------------------------------------------------
__device__ __forceinline__ uint32_t smem_u32(const void* p) {
    return (uint32_t)__cvta_generic_to_shared(p);
}
// SW128 swizzle for 128-byte rows: bits[6:4] ^= bits[9:7]
__device__ __forceinline__ uint32_t swz(uint32_t o) { return o ^ ((o >> 3) & 0x70); }
// swizzle for 256-byte rows: bits[6:4] ^= bits[10:8]
__device__ __forceinline__ uint32_t swzB(uint32_t o) { return o ^ ((o >> 4) & 0x70); }

__device__ __forceinline__ void cp_async16(uint32_t dst, const void* src) {
    asm volatile("cp.async.cg.shared.global [%0], [%1], 16;" :: "r"(dst), "l"(src));
}
__device__ __forceinline__ void cp_commit() {
    asm volatile("cp.async.commit_group;" ::: "memory");
}
__device__ __forceinline__ void cp_wait1() {
    asm volatile("cp.async.wait_group 1;" ::: "memory");
}
__device__ __forceinline__ void ldsm_x4(uint32_t* r, uint32_t addr) {
    asm volatile("ldmatrix.sync.aligned.m8n8.x4.shared.b16 {%0,%1,%2,%3}, [%4];"
                 : "=r"(r[0]), "=r"(r[1]), "=r"(r[2]), "=r"(r[3]) : "r"(addr));
}
__device__ __forceinline__ void ldsm_x4_t(uint32_t* r, uint32_t addr) {
    asm volatile("ldmatrix.sync.aligned.m8n8.x4.trans.shared.b16 {%0,%1,%2,%3}, [%4];"
                 : "=r"(r[0]), "=r"(r[1]), "=r"(r[2]), "=r"(r[3]) : "r"(addr));
}
__device__ __forceinline__ void mma16816(float* c, const uint32_t* a,
                                         uint32_t b0, uint32_t b1) {
    asm volatile("mma.sync.aligned.m16n8k16.row.col.f32.f16.f16.f32 "
                 "{%0,%1,%2,%3}, {%4,%5,%6,%7}, {%8,%9}, {%0,%1,%2,%3};"
                 : "+f"(c[0]), "+f"(c[1]), "+f"(c[2]), "+f"(c[3])
                 : "r"(a[0]), "r"(a[1]), "r"(a[2]), "r"(a[3]), "r"(b0), "r"(b1));
}
// exp(x) for two halfs at once: ex2.approx.f16x2 (inputs pre-scaled by log2e)
__device__ __forceinline__ __half2 h2_ex2(__half2 x) {
    __half2 r;
    asm("ex2.approx.f16x2 %0, %1;" : "=r"(*(uint32_t*)&r) : "r"(*(const uint32_t*)&x));
    return r;
}

// ---------------------------------------------------------------------------
// fp16 tensor-core GEMM, templated on B layout:
//   TRB=0 (NT): C = alpha * A[M,K] @ B[N,K]^T
//   TRB=1 (NN): C = alpha * A[M,K] @ B[K,N]   (ldsm.trans)
// Block tile 128x128, BK=64, 3-stage cp.async ring, 128 threads (4 warps 2x2),
// warp tile 64x64, 2 CTAs/SM, register double-buffering.
// mode 0: half out + fp32 bias(col).   mode 1: float out.   mode 2: half out.
// mode 3: half out = exp(alpha*acc) via f16x2 ex2, psums -> g_ps[row*32+bx*2+wn].
// mode 4: float out * rowinv (aux = inv, row-global index).
// ---------------------------------------------------------------------------
#define BM 128
#define BN 128
#define BKH 64
#define STG 32768
#define NSTAGE 3

template<int TRB>
__global__ __launch_bounds__(128, 2)
void mm_h16(const __half* __restrict__ A, const __half* __restrict__ B,
            const float* __restrict__ aux, void* __restrict__ Cout,
            int lda, int ldb, int ldc,
            size_t zA, size_t zB, size_t zC,
            int K, float alpha, int mode)
{
    extern __shared__ char smem[];
    const uint32_t sbase = smem_u32(smem);
    const int tid = threadIdx.x;
    const int wid = tid >> 5;
    const int lane = tid & 31;

    const int bz = blockIdx.z;
    A += (size_t)bz * zA;
    B += (size_t)bz * zB;

    const int tile_m = blockIdx.y * BM;
    const int tile_n = blockIdx.x * BN;
    const int T = K / BKH;

    // --- A loader: 8 x 16B chunks per thread ---
    const int rA = tid >> 3;
    const int kcA = tid & 7;
    const __half* gA = A + (size_t)(tile_m + rA) * lda + kcA * 8;
    const uint32_t dA = swz((uint32_t)(rA * 128 + kcA * 16));

    // --- B loader ---
    const __half* gB;
    uint32_t dB;
    if (TRB == 0) {
        gB = B + (size_t)(tile_n + rA) * ldb + kcA * 8;
        dB = 16384u + swz((uint32_t)(rA * 128 + kcA * 16));
    } else {
        const int rB = tid >> 4;
        const int cB = tid & 15;
        gB = B + (size_t)rB * ldb + tile_n + cB * 8;
        dB = 16384u + swzB((uint32_t)(rB * 256 + cB * 16));
    }

// A-half and B-half of a stage load, issueable separately.
#define LOAD_A(s, t) do { \
        uint32_t sb_ = sbase + (uint32_t)(s) * STG; \
        const __half* pa_ = gA + (size_t)(t) * BKH; \
        _Pragma("unroll") \
        for (int i_ = 0; i_ < 8; i_++) \
            cp_async16(sb_ + dA + i_ * 2048u, pa_ + (size_t)(16 * i_) * lda); \
    } while (0)
#define LOAD_B(s, t) do { \
        uint32_t sb_ = sbase + (uint32_t)(s) * STG; \
        if (TRB == 0) { \
            const __half* pb_ = gB + (size_t)(t) * BKH; \
            _Pragma("unroll") \
            for (int i_ = 0; i_ < 8; i_++) \
                cp_async16(sb_ + dB + i_ * 2048u, pb_ + (size_t)(16 * i_) * ldb); \
        } else { \
            const __half* pb_ = gB + (size_t)(t) * BKH * ldb; \
            _Pragma("unroll") \
            for (int i_ = 0; i_ < 8; i_++) \
                cp_async16(sb_ + dB + i_ * 2048u, pb_ + (size_t)(8 * i_) * ldb); \
        } \
    } while (0)

    #pragma unroll
    for (int p = 0; p < 2; p++) {
        if (p < T) { LOAD_A(p, p); LOAD_B(p, p); }
        cp_commit();
    }

    // --- compute plan ---
    const int wm = wid & 1;
    const int wn = wid >> 1;
    const int lr = lane & 15;
    const int lcb = (lane >> 4) * 16;

    uint32_t aoff0[4], boff0[4];
    #pragma unroll
    for (int mi = 0; mi < 4; mi++)
        aoff0[mi] = swz((uint32_t)((wm * 64 + mi * 16 + lr) * 128 + lcb));
    if (TRB == 0) {
        #pragma unroll
        for (int nb = 0; nb < 4; nb++)
            boff0[nb] = 16384u + swz((uint32_t)((wn * 64 + nb * 16 + lr) * 128 + lcb));
    } else {
        #pragma unroll
        for (int nb = 0; nb < 4; nb++)
            boff0[nb] = 16384u + swzB((uint32_t)(lr * 256 + wn * 128 + nb * 32 + lcb));
    }

#define LDFRAG(af, bf, sa_, ks_) do { \
        _Pragma("unroll") \
        for (int mi_ = 0; mi_ < 4; mi_++) \
            ldsm_x4((af)[mi_], (sa_) + (aoff0[mi_] ^ (uint32_t)((ks_) * 32))); \
        if (TRB == 0) { \
            _Pragma("unroll") \
            for (int nb_ = 0; nb_ < 4; nb_++) \
                ldsm_x4((bf)[nb_], (sa_) + (boff0[nb_] ^ (uint32_t)((ks_) * 32))); \
        } else { \
            _Pragma("unroll") \
            for (int nb_ = 0; nb_ < 4; nb_++) \
                ldsm_x4_t((bf)[nb_], (sa_) + boff0[nb_] + (uint32_t)((ks_) * 4096)); \
        } \
    } while (0)

#define MMABLK(af, bf) do { \
        _Pragma("unroll") \
        for (int mi_ = 0; mi_ < 4; mi_++) \
            _Pragma("unroll") \
            for (int ni_ = 0; ni_ < 8; ni_++) { \
                uint32_t b0_ = (TRB == 0) ? (bf)[ni_ >> 1][ni_ & 1] \
                                          : (bf)[ni_ >> 1][(ni_ & 1) * 2]; \
                uint32_t b1_ = (TRB == 0) ? (bf)[ni_ >> 1][(ni_ & 1) + 2] \
                                          : (bf)[ni_ >> 1][(ni_ & 1) * 2 + 1]; \
                mma16816(acc[mi_][ni_], (af)[mi_], b0_, b1_); \
            } \
    } while (0)

    float acc[4][8][4] = {};
    uint32_t a0[4][4], b0[4][4], a1[4][4], b1[4][4];

    cp_wait1();
    __syncthreads();
    LDFRAG(a0, b0, sbase, 0);

    for (int t = 0; t < T; t++) {
        const uint32_t sa = sbase + (uint32_t)(t % NSTAGE) * STG;
        const bool pf = (t + 2 < T);
        const int ps = (t + 2) % NSTAGE;

        LDFRAG(a1, b1, sa, 1);
        MMABLK(a0, b0);                // ks 0
        if (pf) LOAD_A(ps, t + 2);     // issue global loads early, mid-compute
        LDFRAG(a0, b0, sa, 2);
        MMABLK(a1, b1);                // ks 1
        if (pf) LOAD_B(ps, t + 2);
        LDFRAG(a1, b1, sa, 3);
        MMABLK(a0, b0);                // ks 2

        cp_commit();
        cp_wait1();
        __syncthreads();

        if (t + 1 < T)
            LDFRAG(a0, b0, sbase + (uint32_t)((t + 1) % NSTAGE) * STG, 0);
        MMABLK(a1, b1);                // ks 3 (covers barrier + next-stage loads)
    }

    // --- epilogue ---
    const int er = lane >> 2;
    const int ec = (lane & 3) * 2;

    if (mode == 1 || mode == 4) {
        float* C = (float*)Cout + (size_t)bz * zC;
        const float* rinv = aux + (size_t)bz * SEQ;
        #pragma unroll
        for (int mi = 0; mi < 4; mi++) {
            int m0 = tile_m + wm * 64 + mi * 16 + er;
            float s0 = alpha, s1 = alpha;
            if (mode == 4) { s0 = rinv[m0]; s1 = rinv[m0 + 8]; }
            #pragma unroll
            for (int ni = 0; ni < 8; ni++) {
                int n0 = tile_n + wn * 64 + ni * 8 + ec;
                float* c = acc[mi][ni];
                *(float2*)(C + (size_t)m0 * ldc + n0) =
                    make_float2(c[0] * s0, c[1] * s0);
                *(float2*)(C + (size_t)(m0 + 8) * ldc + n0) =
                    make_float2(c[2] * s1, c[3] * s1);
            }
        }
    } else {
        __half* C = (__half*)Cout + (size_t)bz * zC;
        float psum[4][2];
        #pragma unroll
        for (int mi = 0; mi < 4; mi++) { psum[mi][0] = 0.f; psum[mi][1] = 0.f; }

        const float l2e_alpha = alpha * 1.4426950408889634f;  // alpha * log2(e)

        #pragma unroll
        for (int mi = 0; mi < 4; mi++) {
            #pragma unroll
            for (int ni = 0; ni < 8; ni++) {
                int m0 = tile_m + wm * 64 + mi * 16 + er;
                int n0 = tile_n + wn * 64 + ni * 8 + ec;
                float* c = acc[mi][ni];
                __half2 h01, h23;
                if (mode == 3) {
                    h01 = h2_ex2(__floats2half2_rn(c[0] * l2e_alpha, c[1] * l2e_alpha));
                    h23 = h2_ex2(__floats2half2_rn(c[2] * l2e_alpha, c[3] * l2e_alpha));
                    float2 f01 = __half22float2(h01);
                    float2 f23 = __half22float2(h23);
                    psum[mi][0] += f01.x + f01.y;
                    psum[mi][1] += f23.x + f23.y;
                } else {
                    float bx = 0.f, by = 0.f;
                    if (mode == 0) { bx = aux[n0]; by = aux[n0 + 1]; }
                    h01 = __floats2half2_rn(c[0] * alpha + bx, c[1] * alpha + by);
                    h23 = __floats2half2_rn(c[2] * alpha + bx, c[3] * alpha + by);
                }
                *(__half2*)(C + (size_t)m0 * ldc + n0) = h01;
                *(__half2*)(C + (size_t)(m0 + 8) * ldc + n0) = h23;
            }
        }

        if (mode == 3) {
            #pragma unroll
            for (int mi = 0; mi < 4; mi++) {
                #pragma unroll
                for (int h = 0; h < 2; h++) {
                    float v = psum[mi][h];
                    v += __shfl_xor_sync(0xffffffffu, v, 1);
                    v += __shfl_xor_sync(0xffffffffu, v, 2);
                    if ((lane & 3) == 0) {
                        int row = bz * SEQ + tile_m + wm * 64 + mi * 16 + er + h * 8;
                        g_ps[(size_t)row * 32 + blockIdx.x * 2 + wn] = v;
                    }
                }
            }
        }
    }
#undef LOAD_A
#undef LOAD_B
#undef LDFRAG
#undef MMABLK
}

// ---------------------------------------------------------------------------
// Combined prep: xh = fp16(x), Wc = fp16([W1;W2]), bc = [b1;b2]
// ---------------------------------------------------------------------------
__global__ __launch_bounds__(256)
void prep_all(const float* __restrict__ x,
              const float* __restrict__ W1, const float* __restrict__ W2,
              const float* __restrict__ b1, const float* __restrict__ b2,
              __half* __restrict__ xh, __half* __restrict__ Wc,
              float* __restrict__ bc)
{
    const long long nx4 = (long long)BATCH * SEQ * DIMD / 4;
    const long long nw4 = (long long)DIMD * DIMD / 4;
    long long i = (long long)blockIdx.x * blockDim.x + threadIdx.x;
    long long stride = (long long)gridDim.x * blockDim.x;

    for (long long j = i; j < nx4; j += stride) {
        float4 v = ((const float4*)x)[j];
        ((__half2*)xh)[2 * j + 0] = __floats2half2_rn(v.x, v.y);
        ((__half2*)xh)[2 * j + 1] = __floats2half2_rn(v.z, v.w);
    }
    for (long long j = i; j < 2 * nw4; j += stride) {
        const float* src = (j < nw4) ? W1 : W2;
        long long k = (j < nw4) ? j : j - nw4;
        float4 v = ((const float4*)src)[k];
        ((__half2*)Wc)[2 * j + 0] = __floats2half2_rn(v.x, v.y);
        ((__half2*)Wc)[2 * j + 1] = __floats2half2_rn(v.z, v.w);
    }
    for (long long j = i; j < 2 * DIMD; j += stride)
        bc[j] = (j < DIMD) ? b1[j] : b2[j - DIMD];
}

// ---------------------------------------------------------------------------
// Finalize: inv[row] = 1 / sum(partials[row][0..31])
// 8 lanes per row: lane loads one float4, 3-hop shuffle reduce.
// ---------------------------------------------------------------------------
__global__ __launch_bounds__(256)
void finalize_inv(const float* __restrict__ ps, float* __restrict__ inv)
{
    const int gt = blockIdx.x * 256 + threadIdx.x;
    const int row = gt >> 3;            // 8 lanes per row
    const int sub = gt & 7;
    if (row >= BATCH * SEQ) return;
    float4 v = ((const float4*)(ps + (size_t)row * 32))[sub];
    float s = v.x + v.y + v.z + v.w;
    s += __shfl_xor_sync(0xffffffffu, s, 1);
    s += __shfl_xor_sync(0xffffffffu, s, 2);
    s += __shfl_xor_sync(0xffffffffu, s, 4);
    if (sub == 0) inv[row] = 1.0f / s;
}

// ---------------------------------------------------------------------------
// Launch
// ---------------------------------------------------------------------------
extern "C" void kernel_launch(void* const* d_in, const int* in_sizes, int n_in,
                              void* d_out, int out_size)
{
    const float* x  = (const float*)d_in[0];
    const float* W1 = (const float*)d_in[1];
    const float* b1 = (const float*)d_in[2];
    const float* W2 = (const float*)d_in[3];
    const float* b2 = (const float*)d_in[4];
    float* out = (float*)d_out;

    __half *pxh, *pWc, *pVKh, *pSh;
    float *pbc, *pps, *pinv;
    cudaGetSymbolAddress((void**)&pxh,  g_xh);
    cudaGetSymbolAddress((void**)&pWc,  g_Wc);
    cudaGetSymbolAddress((void**)&pbc,  g_bc);
    cudaGetSymbolAddress((void**)&pVKh, g_VKh);
    cudaGetSymbolAddress((void**)&pSh,  g_Sh);
    cudaGetSymbolAddress((void**)&pps,  g_ps);
    cudaGetSymbolAddress((void**)&pinv, g_inv);

    const int SMEM_SZ = NSTAGE * STG;  // 98304 per CTA
    cudaFuncSetAttribute(mm_h16<0>, cudaFuncAttributeMaxDynamicSharedMemorySize, SMEM_SZ);
    cudaFuncSetAttribute(mm_h16<1>, cudaFuncAttributeMaxDynamicSharedMemorySize, SMEM_SZ);

    const float scale = 1.0f / 32.0f;  // 1/sqrt(1024)

    // 1. fp32 -> fp16 inputs/weights/biases (one kernel)
    prep_all<<<2048, 256>>>(x, W1, W2, b1, b2, pxh, pWc, pbc);

    // 2. [V | K] = fp16(x @ [W1;W2]^T + [b1;b2]) : M=16384, N=2048, K=1024 (NT)
    mm_h16<0><<<dim3(2 * DIMD / BN, BATCH * SEQ / BM, 1), 128, SMEM_SZ>>>(
        pxh, pWc, pbc, pVKh,
        DIMD, DIMD, 2 * DIMD, 0, 0, 0,
        DIMD, 1.0f, 0);

    // 3. P = fp16(exp(scale * K . V)) + partial row sums (NT, mode 3)
    mm_h16<0><<<dim3(SEQ / BN, SEQ / BM, BATCH), 128, SMEM_SZ>>>(
        pVKh + DIMD, pVKh, nullptr, pSh,
        2 * DIMD, 2 * DIMD, SEQ,
        (size_t)SEQ * 2 * DIMD, (size_t)SEQ * 2 * DIMD, (size_t)SEQ * SEQ,
        DIMD, scale, 3);

    // 4. inv[row] = 1 / rowsum (8 lanes/row, coalesced)
    finalize_inv<<<(BATCH * SEQ * 8 + 255) / 256, 256>>>(pps, pinv);

    // 5. out = inv[row] * (P @ V)  (NN via ldsm.trans, fp32 out, mode 4)
    mm_h16<1><<<dim3(DIMD / BN, SEQ / BM, BATCH), 128, SMEM_SZ>>>(
        pSh, pVKh, pinv, out,
        SEQ, 2 * DIMD, DIMD,
        (size_t)SEQ * SEQ, (size_t)SEQ * 2 * DIMD, (size_t)SEQ * DIMD,
        SEQ, 1.0f, 4);
}

// round 13
// speedup vs baseline: 1.3635x; 1.0003x over previous
#include <cuda_runtime.h>
#include <cuda_fp16.h>
#include <cstdint>

#define DIMD  1024
#define BATCH 8
#define SEQ   2048

// ---------------------------------------------------------------------------
// Scratch (static device memory — no allocations)
// ---------------------------------------------------------------------------
__device__ __half g_xh  [(size_t)BATCH * SEQ * DIMD];      // x fp16
__device__ __half g_Wc  [(size_t)2 * DIMD * DIMD];         // [W1;W2] fp16
__device__ float  g_bc  [2 * DIMD];                        // [b1;b2] fp32
__device__ __half g_VKh [(size_t)BATCH * SEQ * 2 * DIMD];  // cols 0-1023 V(==Q), 1024-2047 K
__device__ __half g_Sh  [(size_t)BATCH * SEQ * SEQ];       // exp(scores) fp16
__device__ float  g_ps  [(size_t)BATCH * SEQ * 32];        // partial row sums

// ---------------------------------------------------------------------------
// Helpers
// ---------------------------------------------------------------------------
__device__ __forceinline__ uint32_t smem_u32(const void* p) {
    return (uint32_t)__cvta_generic_to_shared(p);
}
// SW128 swizzle for 128-byte rows: bits[6:4] ^= bits[9:7]
__device__ __forceinline__ uint32_t swz(uint32_t o) { return o ^ ((o >> 3) & 0x70); }
// swizzle for 256-byte rows: bits[6:4] ^= bits[10:8]
__device__ __forceinline__ uint32_t swzB(uint32_t o) { return o ^ ((o >> 4) & 0x70); }

__device__ __forceinline__ void cp_async16(uint32_t dst, const void* src) {
    asm volatile("cp.async.cg.shared.global [%0], [%1], 16;" :: "r"(dst), "l"(src));
}
__device__ __forceinline__ void cp_commit() {
    asm volatile("cp.async.commit_group;" ::: "memory");
}
__device__ __forceinline__ void cp_wait1() {
    asm volatile("cp.async.wait_group 1;" ::: "memory");
}
__device__ __forceinline__ void ldsm_x4(uint32_t* r, uint32_t addr) {
    asm volatile("ldmatrix.sync.aligned.m8n8.x4.shared.b16 {%0,%1,%2,%3}, [%4];"
                 : "=r"(r[0]), "=r"(r[1]), "=r"(r[2]), "=r"(r[3]) : "r"(addr));
}
__device__ __forceinline__ void ldsm_x4_t(uint32_t* r, uint32_t addr) {
    asm volatile("ldmatrix.sync.aligned.m8n8.x4.trans.shared.b16 {%0,%1,%2,%3}, [%4];"
                 : "=r"(r[0]), "=r"(r[1]), "=r"(r[2]), "=r"(r[3]) : "r"(addr));
}
__device__ __forceinline__ void mma16816(float* c, const uint32_t* a,
                                         uint32_t b0, uint32_t b1) {
    asm volatile("mma.sync.aligned.m16n8k16.row.col.f32.f16.f16.f32 "
                 "{%0,%1,%2,%3}, {%4,%5,%6,%7}, {%8,%9}, {%0,%1,%2,%3};"
                 : "+f"(c[0]), "+f"(c[1]), "+f"(c[2]), "+f"(c[3])
                 : "r"(a[0]), "r"(a[1]), "r"(a[2]), "r"(a[3]), "r"(b0), "r"(b1));
}
// exp(x) for two halfs at once: ex2.approx.f16x2 (inputs pre-scaled by log2e)
__device__ __forceinline__ __half2 h2_ex2(__half2 x) {
    __half2 r;
    asm("ex2.approx.f16x2 %0, %1;" : "=r"(*(uint32_t*)&r) : "r"(*(const uint32_t*)&x));
    return r;
}

// ---------------------------------------------------------------------------
// fp16 tensor-core GEMM, templated on B layout:
//   TRB=0 (NT): C = alpha * A[M,K] @ B[N,K]^T
//   TRB=1 (NN): C = alpha * A[M,K] @ B[K,N]   (ldsm.trans)
// Block tile 128x128, BK=64, 3-stage cp.async ring, 128 threads (4 warps 2x2),
// warp tile 64x64, 2 CTAs/SM, register double-buffering, early global issue.
// mode 0: half out + fp32 bias(col).   mode 1: float out.   mode 2: half out.
// mode 3: half out = exp(alpha*acc) via f16x2 ex2, psums -> g_ps[row*32+bx*2+wn].
// mode 4: float out * rowinv; inv computed in-prologue from g_ps into smem.
// ---------------------------------------------------------------------------
#define BM 128
#define BN 128
#define BKH 64
#define STG 32768
#define NSTAGE 3
#define SMEM_SZ (NSTAGE * STG + 512)

template<int TRB>
__global__ __launch_bounds__(128, 2)
void mm_h16(const __half* __restrict__ A, const __half* __restrict__ B,
            const float* __restrict__ aux, void* __restrict__ Cout,
            int lda, int ldb, int ldc,
            size_t zA, size_t zB, size_t zC,
            int K, float alpha, int mode)
{
    extern __shared__ char smem[];
    const uint32_t sbase = smem_u32(smem);
    float* sinv = (float*)(smem + NSTAGE * STG);   // 128 floats (mode 4)
    const int tid = threadIdx.x;
    const int wid = tid >> 5;
    const int lane = tid & 31;

    const int bz = blockIdx.z;
    A += (size_t)bz * zA;
    B += (size_t)bz * zB;

    const int tile_m = blockIdx.y * BM;
    const int tile_n = blockIdx.x * BN;
    const int T = K / BKH;

    // --- A loader: 8 x 16B chunks per thread ---
    const int rA = tid >> 3;
    const int kcA = tid & 7;
    const __half* gA = A + (size_t)(tile_m + rA) * lda + kcA * 8;
    const uint32_t dA = swz((uint32_t)(rA * 128 + kcA * 16));

    // --- B loader ---
    const __half* gB;
    uint32_t dB;
    if (TRB == 0) {
        gB = B + (size_t)(tile_n + rA) * ldb + kcA * 8;
        dB = 16384u + swz((uint32_t)(rA * 128 + kcA * 16));
    } else {
        const int rB = tid >> 4;
        const int cB = tid & 15;
        gB = B + (size_t)rB * ldb + tile_n + cB * 8;
        dB = 16384u + swzB((uint32_t)(rB * 256 + cB * 16));
    }

// A-half and B-half of a stage load, issueable separately.
#define LOAD_A(s, t) do { \
        uint32_t sb_ = sbase + (uint32_t)(s) * STG; \
        const __half* pa_ = gA + (size_t)(t) * BKH; \
        _Pragma("unroll") \
        for (int i_ = 0; i_ < 8; i_++) \
            cp_async16(sb_ + dA + i_ * 2048u, pa_ + (size_t)(16 * i_) * lda); \
    } while (0)
#define LOAD_B(s, t) do { \
        uint32_t sb_ = sbase + (uint32_t)(s) * STG; \
        if (TRB == 0) { \
            const __half* pb_ = gB + (size_t)(t) * BKH; \
            _Pragma("unroll") \
            for (int i_ = 0; i_ < 8; i_++) \
                cp_async16(sb_ + dB + i_ * 2048u, pb_ + (size_t)(16 * i_) * ldb); \
        } else { \
            const __half* pb_ = gB + (size_t)(t) * BKH * ldb; \
            _Pragma("unroll") \
            for (int i_ = 0; i_ < 8; i_++) \
                cp_async16(sb_ + dB + i_ * 2048u, pb_ + (size_t)(8 * i_) * ldb); \
        } \
    } while (0)

    #pragma unroll
    for (int p = 0; p < 2; p++) {
        if (p < T) { LOAD_A(p, p); LOAD_B(p, p); }
        cp_commit();
    }

    // mode 4: compute 1/rowsum for this CTA's 128 rows while cp.async streams.
    // Row per thread; 8 coalesced float4 loads from g_ps; visible after the
    // first __syncthreads below.
    if (mode == 4) {
        const float* p = g_ps + ((size_t)(bz * SEQ + tile_m + tid)) * 32;
        float s = 0.f;
        #pragma unroll
        for (int i = 0; i < 8; i++) {
            float4 v = ((const float4*)p)[i];
            s += (v.x + v.y) + (v.z + v.w);
        }
        sinv[tid] = 1.0f / s;
    }

    // --- compute plan ---
    const int wm = wid & 1;
    const int wn = wid >> 1;
    const int lr = lane & 15;
    const int lcb = (lane >> 4) * 16;

    uint32_t aoff0[4], boff0[4];
    #pragma unroll
    for (int mi = 0; mi < 4; mi++)
        aoff0[mi] = swz((uint32_t)((wm * 64 + mi * 16 + lr) * 128 + lcb));
    if (TRB == 0) {
        #pragma unroll
        for (int nb = 0; nb < 4; nb++)
            boff0[nb] = 16384u + swz((uint32_t)((wn * 64 + nb * 16 + lr) * 128 + lcb));
    } else {
        #pragma unroll
        for (int nb = 0; nb < 4; nb++)
            boff0[nb] = 16384u + swzB((uint32_t)(lr * 256 + wn * 128 + nb * 32 + lcb));
    }

#define LDFRAG(af, bf, sa_, ks_) do { \
        _Pragma("unroll") \
        for (int mi_ = 0; mi_ < 4; mi_++) \
            ldsm_x4((af)[mi_], (sa_) + (aoff0[mi_] ^ (uint32_t)((ks_) * 32))); \
        if (TRB == 0) { \
            _Pragma("unroll") \
            for (int nb_ = 0; nb_ < 4; nb_++) \
                ldsm_x4((bf)[nb_], (sa_) + (boff0[nb_] ^ (uint32_t)((ks_) * 32))); \
        } else { \
            _Pragma("unroll") \
            for (int nb_ = 0; nb_ < 4; nb_++) \
                ldsm_x4_t((bf)[nb_], (sa_) + boff0[nb_] + (uint32_t)((ks_) * 4096)); \
        } \
    } while (0)

#define MMABLK(af, bf) do { \
        _Pragma("unroll") \
        for (int mi_ = 0; mi_ < 4; mi_++) \
            _Pragma("unroll") \
            for (int ni_ = 0; ni_ < 8; ni_++) { \
                uint32_t b0_ = (TRB == 0) ? (bf)[ni_ >> 1][ni_ & 1] \
                                          : (bf)[ni_ >> 1][(ni_ & 1) * 2]; \
                uint32_t b1_ = (TRB == 0) ? (bf)[ni_ >> 1][(ni_ & 1) + 2] \
                                          : (bf)[ni_ >> 1][(ni_ & 1) * 2 + 1]; \
                mma16816(acc[mi_][ni_], (af)[mi_], b0_, b1_); \
            } \
    } while (0)

    float acc[4][8][4] = {};
    uint32_t a0[4][4], b0[4][4], a1[4][4], b1[4][4];

    cp_wait1();
    __syncthreads();
    LDFRAG(a0, b0, sbase, 0);

    for (int t = 0; t < T; t++) {
        const uint32_t sa = sbase + (uint32_t)(t % NSTAGE) * STG;
        const bool pf = (t + 2 < T);
        const int ps = (t + 2) % NSTAGE;

        LDFRAG(a1, b1, sa, 1);
        MMABLK(a0, b0);                // ks 0
        if (pf) LOAD_A(ps, t + 2);     // issue global loads early, mid-compute
        LDFRAG(a0, b0, sa, 2);
        MMABLK(a1, b1);                // ks 1
        if (pf) LOAD_B(ps, t + 2);
        LDFRAG(a1, b1, sa, 3);
        MMABLK(a0, b0);                // ks 2

        cp_commit();
        cp_wait1();
        __syncthreads();

        if (t + 1 < T)
            LDFRAG(a0, b0, sbase + (uint32_t)((t + 1) % NSTAGE) * STG, 0);
        MMABLK(a1, b1);                // ks 3 (covers barrier + next-stage loads)
    }

    // --- epilogue ---
    const int er = lane >> 2;
    const int ec = (lane & 3) * 2;

    if (mode == 1 || mode == 4) {
        float* C = (float*)Cout + (size_t)bz * zC;
        #pragma unroll
        for (int mi = 0; mi < 4; mi++) {
            int mrow = wm * 64 + mi * 16 + er;
            int m0 = tile_m + mrow;
            float s0 = alpha, s1 = alpha;
            if (mode == 4) { s0 = sinv[mrow]; s1 = sinv[mrow + 8]; }
            #pragma unroll
            for (int ni = 0; ni < 8; ni++) {
                int n0 = tile_n + wn * 64 + ni * 8 + ec;
                float* c = acc[mi][ni];
                *(float2*)(C + (size_t)m0 * ldc + n0) =
                    make_float2(c[0] * s0, c[1] * s0);
                *(float2*)(C + (size_t)(m0 + 8) * ldc + n0) =
                    make_float2(c[2] * s1, c[3] * s1);
            }
        }
    } else {
        __half* C = (__half*)Cout + (size_t)bz * zC;
        float psum[4][2];
        #pragma unroll
        for (int mi = 0; mi < 4; mi++) { psum[mi][0] = 0.f; psum[mi][1] = 0.f; }

        const float l2e_alpha = alpha * 1.4426950408889634f;  // alpha * log2(e)

        #pragma unroll
        for (int mi = 0; mi < 4; mi++) {
            #pragma unroll
            for (int ni = 0; ni < 8; ni++) {
                int m0 = tile_m + wm * 64 + mi * 16 + er;
                int n0 = tile_n + wn * 64 + ni * 8 + ec;
                float* c = acc[mi][ni];
                __half2 h01, h23;
                if (mode == 3) {
                    h01 = h2_ex2(__floats2half2_rn(c[0] * l2e_alpha, c[1] * l2e_alpha));
                    h23 = h2_ex2(__floats2half2_rn(c[2] * l2e_alpha, c[3] * l2e_alpha));
                    float2 f01 = __half22float2(h01);
                    float2 f23 = __half22float2(h23);
                    psum[mi][0] += f01.x + f01.y;
                    psum[mi][1] += f23.x + f23.y;
                } else {
                    float bx = 0.f, by = 0.f;
                    if (mode == 0) { bx = aux[n0]; by = aux[n0 + 1]; }
                    h01 = __floats2half2_rn(c[0] * alpha + bx, c[1] * alpha + by);
                    h23 = __floats2half2_rn(c[2] * alpha + bx, c[3] * alpha + by);
                }
                *(__half2*)(C + (size_t)m0 * ldc + n0) = h01;
                *(__half2*)(C + (size_t)(m0 + 8) * ldc + n0) = h23;
            }
        }

        if (mode == 3) {
            #pragma unroll
            for (int mi = 0; mi < 4; mi++) {
                #pragma unroll
                for (int h = 0; h < 2; h++) {
                    float v = psum[mi][h];
                    v += __shfl_xor_sync(0xffffffffu, v, 1);
                    v += __shfl_xor_sync(0xffffffffu, v, 2);
                    if ((lane & 3) == 0) {
                        int row = bz * SEQ + tile_m + wm * 64 + mi * 16 + er + h * 8;
                        g_ps[(size_t)row * 32 + blockIdx.x * 2 + wn] = v;
                    }
                }
            }
        }
    }
#undef LOAD_A
#undef LOAD_B
#undef LDFRAG
#undef MMABLK
}

// ---------------------------------------------------------------------------
// Combined prep: xh = fp16(x), Wc = fp16([W1;W2]), bc = [b1;b2]
// ---------------------------------------------------------------------------
__global__ __launch_bounds__(256)
void prep_all(const float* __restrict__ x,
              const float* __restrict__ W1, const float* __restrict__ W2,
              const float* __restrict__ b1, const float* __restrict__ b2,
              __half* __restrict__ xh, __half* __restrict__ Wc,
              float* __restrict__ bc)
{
    const long long nx4 = (long long)BATCH * SEQ * DIMD / 4;
    const long long nw4 = (long long)DIMD * DIMD / 4;
    long long i = (long long)blockIdx.x * blockDim.x + threadIdx.x;
    long long stride = (long long)gridDim.x * blockDim.x;

    for (long long j = i; j < nx4; j += stride) {
        float4 v = ((const float4*)x)[j];
        ((__half2*)xh)[2 * j + 0] = __floats2half2_rn(v.x, v.y);
        ((__half2*)xh)[2 * j + 1] = __floats2half2_rn(v.z, v.w);
    }
    for (long long j = i; j < 2 * nw4; j += stride) {
        const float* src = (j < nw4) ? W1 : W2;
        long long k = (j < nw4) ? j : j - nw4;
        float4 v = ((const float4*)src)[k];
        ((__half2*)Wc)[2 * j + 0] = __floats2half2_rn(v.x, v.y);
        ((__half2*)Wc)[2 * j + 1] = __floats2half2_rn(v.z, v.w);
    }
    for (long long j = i; j < 2 * DIMD; j += stride)
        bc[j] = (j < DIMD) ? b1[j] : b2[j - DIMD];
}

// ---------------------------------------------------------------------------
// Launch
// ---------------------------------------------------------------------------
extern "C" void kernel_launch(void* const* d_in, const int* in_sizes, int n_in,
                              void* d_out, int out_size)
{
    const float* x  = (const float*)d_in[0];
    const float* W1 = (const float*)d_in[1];
    const float* b1 = (const float*)d_in[2];
    const float* W2 = (const float*)d_in[3];
    const float* b2 = (const float*)d_in[4];
    float* out = (float*)d_out;

    __half *pxh, *pWc, *pVKh, *pSh;
    float *pbc;
    cudaGetSymbolAddress((void**)&pxh,  g_xh);
    cudaGetSymbolAddress((void**)&pWc,  g_Wc);
    cudaGetSymbolAddress((void**)&pbc,  g_bc);
    cudaGetSymbolAddress((void**)&pVKh, g_VKh);
    cudaGetSymbolAddress((void**)&pSh,  g_Sh);

    cudaFuncSetAttribute(mm_h16<0>, cudaFuncAttributeMaxDynamicSharedMemorySize, SMEM_SZ);
    cudaFuncSetAttribute(mm_h16<1>, cudaFuncAttributeMaxDynamicSharedMemorySize, SMEM_SZ);

    const float scale = 1.0f / 32.0f;  // 1/sqrt(1024)

    // 1. fp32 -> fp16 inputs/weights/biases (one kernel)
    prep_all<<<2048, 256>>>(x, W1, W2, b1, b2, pxh, pWc, pbc);

    // 2. [V | K] = fp16(x @ [W1;W2]^T + [b1;b2]) : M=16384, N=2048, K=1024 (NT)
    mm_h16<0><<<dim3(2 * DIMD / BN, BATCH * SEQ / BM, 1), 128, SMEM_SZ>>>(
        pxh, pWc, pbc, pVKh,
        DIMD, DIMD, 2 * DIMD, 0, 0, 0,
        DIMD, 1.0f, 0);

    // 3. P = fp16(exp(scale * K . V)) + partial row sums (NT, mode 3)
    mm_h16<0><<<dim3(SEQ / BN, SEQ / BM, BATCH), 128, SMEM_SZ>>>(
        pVKh + DIMD, pVKh, nullptr, pSh,
        2 * DIMD, 2 * DIMD, SEQ,
        (size_t)SEQ * 2 * DIMD, (size_t)SEQ * 2 * DIMD, (size_t)SEQ * SEQ,
        DIMD, scale, 3);

    // 4. out = inv[row] * (P @ V)  (NN via ldsm.trans, inv computed in-prologue)
    mm_h16<1><<<dim3(DIMD / BN, SEQ / BM, BATCH), 128, SMEM_SZ>>>(
        pSh, pVKh, nullptr, out,
        SEQ, 2 * DIMD, DIMD,
        (size_t)SEQ * SEQ, (size_t)SEQ * 2 * DIMD, (size_t)SEQ * DIMD,
        SEQ, 1.0f, 4);
}